// round 11
// baseline (speedup 1.0000x reference)
#include <cuda_runtime.h>
#include <cuda_bf16.h>
#include <cuda_fp16.h>
#include <math.h>
#include <stdint.h>

#define SEQ   2048
#define HID   4096
#define HEADS 32
#define HDIM  128
#define QKVN  12288
#define KPAD  4160          // 4096 + 64 ext cols (zero-correction)
#define NCH   130           // KPAD / 32

// ---------------- scratch ----------------
__device__ float g_proj[(size_t)SEQ * QKVN];
__device__ float g_attn[(size_t)SEQ * HID];
__device__ float g_cos[SEQ * 64];
__device__ float g_sin[SEQ * 64];
__device__ float g_R[(size_t)32 * QKVN];
__device__ __half g_ah[(size_t)SEQ * KPAD];
__device__ __half g_al[(size_t)SEQ * KPAD];
__device__ __half g_bq[(size_t)QKVN * KPAD];
__device__ __nv_bfloat16 g_qh[(size_t)HEADS * SEQ * HDIM];
__device__ __nv_bfloat16 g_ql[(size_t)HEADS * SEQ * HDIM];
__device__ __nv_bfloat16 g_kh[(size_t)HEADS * SEQ * HDIM];
__device__ __nv_bfloat16 g_kl[(size_t)HEADS * SEQ * HDIM];
__device__ __nv_bfloat16 g_vth[(size_t)HEADS * HDIM * SEQ];
__device__ __nv_bfloat16 g_vtl[(size_t)HEADS * HDIM * SEQ];

__device__ __forceinline__ float neg_inf() { return __int_as_float(0xff800000); }

__device__ __forceinline__ uint32_t smem_to_u32(const void* p) {
    uint32_t a;
    asm("{ .reg .u64 t; cvta.to.shared.u64 t, %1; cvt.u32.u64 %0, t; }" : "=r"(a) : "l"(p));
    return a;
}
__device__ __forceinline__ void cp_async16(uint32_t dst, const void* src) {
    asm volatile("cp.async.cg.shared.global [%0], [%1], 16;" :: "r"(dst), "l"(src));
}
#define CP_COMMIT() asm volatile("cp.async.commit_group;" ::: "memory")
#define CP_WAIT(n)  asm volatile("cp.async.wait_group %0;" :: "n"(n) : "memory")

#define LDSM_X4(r, a) \
    asm volatile("ldmatrix.sync.aligned.m8n8.x4.shared.b16 {%0,%1,%2,%3}, [%4];" \
        : "=r"((r)[0]), "=r"((r)[1]), "=r"((r)[2]), "=r"((r)[3]) : "r"(a))
#define LDSM_X2(r, a) \
    asm volatile("ldmatrix.sync.aligned.m8n8.x2.shared.b16 {%0,%1}, [%2];" \
        : "=r"((r)[0]), "=r"((r)[1]) : "r"(a))
#define MMA_BF16(d, a, b) \
    asm volatile("mma.sync.aligned.m16n8k16.row.col.f32.bf16.bf16.f32 " \
        "{%0,%1,%2,%3}, {%4,%5,%6,%7}, {%8,%9}, {%0,%1,%2,%3};" \
        : "+f"((d)[0]), "+f"((d)[1]), "+f"((d)[2]), "+f"((d)[3]) \
        : "r"((a)[0]), "r"((a)[1]), "r"((a)[2]), "r"((a)[3]), "r"((b)[0]), "r"((b)[1]))
#define MMA_F16(d, a, b) \
    asm volatile("mma.sync.aligned.m16n8k16.row.col.f32.f16.f16.f32 " \
        "{%0,%1,%2,%3}, {%4,%5,%6,%7}, {%8,%9}, {%0,%1,%2,%3};" \
        : "+f"((d)[0]), "+f"((d)[1]), "+f"((d)[2]), "+f"((d)[3]) \
        : "r"((a)[0]), "r"((a)[1]), "r"((a)[2]), "r"((a)[3]), "r"((b)[0]), "r"((b)[1]))

__device__ __forceinline__ uint32_t swz(int r, int kbyte) {
    uint32_t seg = ((uint32_t)(kbyte >> 4)) ^ (((uint32_t)r >> 1) & 3u);
    return (uint32_t)r * 64u + (seg << 4) + (uint32_t)(kbyte & 15);
}

// ---------------- RoPE tables ----------------
__global__ void rope_tables_kernel(const int* __restrict__ pos_ids) {
    int s = blockIdx.x;
    int d = threadIdx.x;
    double inv = pow(10000.0, -(double)(2 * d) / 128.0);
    double ang = (double)pos_ids[s] * inv;
    g_cos[s * 64 + d] = (float)cos(ang);
    g_sin[s * 64 + d] = (float)sin(ang);
}

// ---------------- fused fp32 -> fp16 hi/lo split + group rowsums (validated R8) -------
__global__ __launch_bounds__(256)
void split_rowsum_kernel(const float* __restrict__ X, __half* __restrict__ H,
                         __half* __restrict__ L) {
    int m = blockIdx.x;
    const float* row = X + (size_t)m * 4096;
    int t = threadIdx.x;
    float s = 0.f;
    size_t o = (size_t)m * KPAD + t * 16;
    #pragma unroll
    for (int j = 0; j < 4; j++) {
        float4 v = *(const float4*)(row + t * 16 + j * 4);
        __half h0 = __float2half_rn(v.x), h1 = __float2half_rn(v.y);
        __half h2 = __float2half_rn(v.z), h3 = __float2half_rn(v.w);
        H[o + j * 4 + 0] = h0; H[o + j * 4 + 1] = h1;
        H[o + j * 4 + 2] = h2; H[o + j * 4 + 3] = h3;
        L[o + j * 4 + 0] = __float2half_rn(v.x - __half2float(h0));
        L[o + j * 4 + 1] = __float2half_rn(v.y - __half2float(h1));
        L[o + j * 4 + 2] = __float2half_rn(v.z - __half2float(h2));
        L[o + j * 4 + 3] = __float2half_rn(v.w - __half2float(h3));
        s += v.x + v.y + v.z + v.w;
    }
    s += __shfl_xor_sync(0xffffffffu, s, 1);
    s += __shfl_xor_sync(0xffffffffu, s, 2);
    s += __shfl_xor_sync(0xffffffffu, s, 4);
    if ((t & 7) == 0) {
        int g = t >> 3;
        __half h = __float2half_rn(s);
        __half lo = __float2half_rn(s - __half2float(h));
        size_t e = (size_t)m * KPAD + 4096 + g;
        H[e] = h; H[e + 32] = h;
        L[e] = lo; L[e + 32] = lo;
    }
}

// ---------------- q transpose (coalesced, validated R8) ----------------
__global__ __launch_bounds__(256)
void qT_kernel(const int* __restrict__ Qw, __half* __restrict__ B, int N) {
    __shared__ int w[64][65];
    int n0 = blockIdx.x * 64, k0 = blockIdx.y * 64;
    int tid = threadIdx.x;
    int tx = tid & 15, ty = tid >> 4;
    #pragma unroll
    for (int p = 0; p < 4; p++) {
        int r = p * 16 + ty;
        int4 v = *(const int4*)(Qw + (size_t)(k0 + r) * N + n0 + tx * 4);
        w[r][tx * 4 + 0] = v.x; w[r][tx * 4 + 1] = v.y;
        w[r][tx * 4 + 2] = v.z; w[r][tx * 4 + 3] = v.w;
    }
    __syncthreads();
    int kx = tid & 7, ny = tid >> 3;
    #pragma unroll
    for (int p = 0; p < 2; p++) {
        int n = p * 32 + ny;
        __half h[8];
        #pragma unroll
        for (int j = 0; j < 8; j++) h[j] = __float2half_rn((float)w[kx * 8 + j][n]);
        *(uint4*)(B + (size_t)(n0 + n) * KPAD + k0 + kx * 8) = *(uint4*)h;
    }
}

// ---------------- scale prep (parallel, validated R9) ----------------
__global__ __launch_bounds__(256)
void prep_scales_kernel(const float* __restrict__ S, const float* __restrict__ Z,
                        float* __restrict__ R, __half* __restrict__ B, int N) {
    __shared__ float sp[32][33];
    int nl = threadIdx.x & 31, tg = threadIdx.x >> 5;
    int n = blockIdx.x * 32 + nl;
    #pragma unroll
    for (int j = 0; j < 4; j++) {
        int g = tg * 4 + j;
        float s = S[(size_t)g * N + n];
        float z = Z[(size_t)g * N + n];
        sp[g][nl] = fmaxf(s, 1e-30f);
        float t = -s * z;
        __half th = __float2half_rn(t);
        B[(size_t)n * KPAD + 4096 + g] = th;
        B[(size_t)n * KPAD + 4128 + g] = __float2half_rn(t - __half2float(th));
    }
    __syncthreads();
    #pragma unroll
    for (int j = 0; j < 4; j++) {
        int g = tg * 4 + j;
        R[(size_t)g * N + n] = (g < 31) ? sp[g][nl] / sp[g + 1][nl] : sp[31][nl];
    }
}

// ---------------- exact-q fp16 GEMM, 256 threads, warp 64x64 (R7, best measured) ------
#define GST_AH 0
#define GST_AL 8192
#define GST_B  16384
#define GSTAGE 32768

__global__ __launch_bounds__(256, 1)
void gemm_q_kernel(const __half* __restrict__ Ah, const __half* __restrict__ Al,
                   const __half* __restrict__ B, const float* __restrict__ R,
                   float* __restrict__ C, int M, int N) {
    extern __shared__ char smraw[];
    const uint32_t sb = smem_to_u32(smraw);
    const int tid = threadIdx.x, lane = tid & 31, wid = tid >> 5;
    const int m0 = blockIdx.x << 7, n0 = blockIdx.y << 8;
    const int wm = (wid & 1) << 6;
    const int wn = (wid >> 1) << 6;

    float acc[4][8][4];
    #pragma unroll
    for (int mi = 0; mi < 4; mi++)
        #pragma unroll
        for (int ni = 0; ni < 8; ni++)
            #pragma unroll
            for (int e = 0; e < 4; e++) acc[mi][ni][e] = 0.f;

    auto load_stage = [&](int buf, int c) {
        uint32_t stage = sb + (uint32_t)buf * GSTAGE;
        int k0 = c << 5;
        #pragma unroll
        for (int u = 0; u < 4; u++) {
            int idx = tid + u * 256;
            int hl = idx >> 9;
            int r = (idx & 511) >> 2, seg = idx & 3;
            const __half* src = hl ? Al : Ah;
            cp_async16(stage + (hl ? GST_AL : GST_AH) + swz(r, seg << 4),
                       src + (size_t)(m0 + r) * KPAD + k0 + seg * 8);
        }
        #pragma unroll
        for (int u = 0; u < 4; u++) {
            int idx = tid + u * 256;
            int r = idx >> 2, seg = idx & 3;
            cp_async16(stage + GST_B + swz(r, seg << 4),
                       B + (size_t)(n0 + r) * KPAD + k0 + seg * 8);
        }
        CP_COMMIT();
    };

    load_stage(0, 0);
    load_stage(1, 1);

    float rv[16];
    int buf = 0;
    for (int i = 0; i < NCH; i++) {
        if (i + 2 < NCH) {
            int nb = buf + 2; if (nb >= 3) nb -= 3;
            load_stage(nb, i + 2);
            CP_WAIT(2);
        } else if (i + 1 < NCH) {
            CP_WAIT(1);
        } else {
            CP_WAIT(0);
        }
        __syncthreads();

        if ((i & 3) == 0 && i < 128) {
            int g = i >> 2;
            #pragma unroll
            for (int j = 0; j < 16; j++)
                rv[j] = __ldg(&R[(size_t)g * N + n0 + wn + (j >> 1) * 8
                                 + (lane & 3) * 2 + (j & 1)]);
        }

        uint32_t stage = sb + (uint32_t)buf * GSTAGE;
        #pragma unroll
        for (int ks = 0; ks < 2; ks++) {
            uint32_t a_h[4][4], a_l[4][4];
            int akb = ks * 32 + ((lane >> 4) & 1) * 16;
            #pragma unroll
            for (int mi = 0; mi < 4; mi++) {
                int row = wm + mi * 16 + (lane & 15);
                uint32_t so = swz(row, akb);
                LDSM_X4(a_h[mi], stage + GST_AH + so);
                LDSM_X4(a_l[mi], stage + GST_AL + so);
            }
            int bkb = ks * 32 + ((lane >> 3) & 1) * 16;
            #pragma unroll
            for (int ni = 0; ni < 8; ni++) {
                uint32_t b[2];
                int row = wn + ni * 8 + (lane & 7);
                LDSM_X2(b, stage + GST_B + swz(row, bkb));
                #pragma unroll
                for (int mi = 0; mi < 4; mi++) {
                    MMA_F16(acc[mi][ni], a_h[mi], b);
                    MMA_F16(acc[mi][ni], a_l[mi], b);
                }
            }
        }

        if ((i & 3) == 3 && i < 128) {
            #pragma unroll
            for (int mi = 0; mi < 4; mi++)
                #pragma unroll
                for (int ni = 0; ni < 8; ni++) {
                    acc[mi][ni][0] *= rv[ni * 2];
                    acc[mi][ni][1] *= rv[ni * 2 + 1];
                    acc[mi][ni][2] *= rv[ni * 2];
                    acc[mi][ni][3] *= rv[ni * 2 + 1];
                }
        }
        __syncthreads();
        if (++buf == 3) buf = 0;
    }

    const int er = m0 + wm + (lane >> 2);
    const int ec = n0 + wn + (lane & 3) * 2;
    #pragma unroll
    for (int mi = 0; mi < 4; mi++) {
        #pragma unroll
        for (int ni = 0; ni < 8; ni++) {
            float* p = C + (size_t)(er + mi * 16) * N + ec + ni * 8;
            *(float2*)p                   = make_float2(acc[mi][ni][0], acc[mi][ni][1]);
            *(float2*)(p + 8 * (size_t)N) = make_float2(acc[mi][ni][2], acc[mi][ni][3]);
        }
    }
}

// ---------------- RoPE + split Q/K -> bf16 hi/lo [h][s][d] ----------------
__global__ __launch_bounds__(256)
void rope_split_kernel() {
    int s = blockIdx.x;
    const float* row = g_proj + (size_t)s * QKVN;
    for (int it = threadIdx.x; it < 4096; it += 256) {
        int qk = it >> 11;
        int hh = (it >> 6) & 31;
        int d  = it & 63;
        float c = g_cos[s * 64 + d], sn = g_sin[s * 64 + d];
        const float* p = row + qk * HID + hh * 128;
        float x1 = p[d], x2 = p[d + 64];
        float y1 = x1 * c - x2 * sn;
        float y2 = x2 * c + x1 * sn;
        if (qk == 0) { y1 *= 0.08838834764831845f; y2 *= 0.08838834764831845f; }
        __nv_bfloat16* H = qk ? g_kh : g_qh;
        __nv_bfloat16* L = qk ? g_kl : g_ql;
        size_t o = ((size_t)hh * SEQ + s) * 128 + d;
        __nv_bfloat16 h1 = __float2bfloat16(y1), h2 = __float2bfloat16(y2);
        H[o] = h1; H[o + 64] = h2;
        L[o]      = __float2bfloat16(y1 - __bfloat162float(h1));
        L[o + 64] = __float2bfloat16(y2 - __bfloat162float(h2));
    }
}

// ---------------- V transpose + split ----------------
__global__ void v_transpose_split_kernel() {
    __shared__ float t[32][33];
    int s0 = blockIdx.x * 32, d0 = blockIdx.y * 32, h = blockIdx.z;
    int tx = threadIdx.x, ty = threadIdx.y;
    #pragma unroll
    for (int rr = 0; rr < 32; rr += 8)
        t[rr + ty][tx] = g_proj[(size_t)(s0 + rr + ty) * QKVN + 2 * HID + h * 128 + d0 + tx];
    __syncthreads();
    #pragma unroll
    for (int rr = 0; rr < 32; rr += 8) {
        int d = d0 + rr + ty;
        float v = t[tx][rr + ty];
        __nv_bfloat16 hi = __float2bfloat16(v);
        size_t o = ((size_t)h * 128 + d) * SEQ + s0 + tx;
        g_vth[o] = hi;
        g_vtl[o] = __float2bfloat16(v - __bfloat162float(hi));
    }
}

// ---------------- bf16x3 mma.sync flash attention (R7 core, best measured) ------------
#define QPITCH 272
#define VPITCH 144
#define AT_QH  0
#define AT_QL  17408
#define AT_K0  34816
#define KV_KH  0
#define KV_KL  17408
#define KV_VH  34816
#define KV_VL  53248
#define AT_STAGE 71680
#define AT_SMEM  (AT_K0 + 2 * AT_STAGE)   // 178176

__global__ __launch_bounds__(128, 1)
void attn_mma_kernel(float* __restrict__ out) {
    extern __shared__ char smraw[];
    const uint32_t sb = smem_to_u32(smraw);
    const int h  = blockIdx.x;
    const int qt = (int)gridDim.y - 1 - (int)blockIdx.y;
    const int tid = threadIdx.x, lane = tid & 31, warp = tid >> 5;
    const int wm16 = warp << 4;

    const __nv_bfloat16* qhp = g_qh + ((size_t)h * SEQ + qt * 64) * 128;
    const __nv_bfloat16* qlp = g_ql + ((size_t)h * SEQ + qt * 64) * 128;
    const __nv_bfloat16* kh0 = g_kh + (size_t)h * SEQ * 128;
    const __nv_bfloat16* kl0 = g_kl + (size_t)h * SEQ * 128;
    const __nv_bfloat16* vh0 = g_vth + (size_t)h * 128 * SEQ;
    const __nv_bfloat16* vl0 = g_vtl + (size_t)h * 128 * SEQ;

    auto load_kv = [&](int kt_, int buf_) {
        uint32_t base = sb + AT_K0 + (uint32_t)buf_ * AT_STAGE;
        const __nv_bfloat16* kh = kh0 + (size_t)kt_ * 64 * 128;
        const __nv_bfloat16* kl = kl0 + (size_t)kt_ * 64 * 128;
        #pragma unroll
        for (int u = 0; u < 16; u++) {
            int i = tid + u * 128;
            int m = i >> 10, c = i & 1023, r = c >> 4, seg = c & 15;
            cp_async16(base + m * 17408 + r * QPITCH + seg * 16,
                       (m ? kl : kh) + r * 128 + seg * 8);
        }
        const __nv_bfloat16* vh = vh0 + kt_ * 64;
        const __nv_bfloat16* vl = vl0 + kt_ * 64;
        #pragma unroll
        for (int u = 0; u < 16; u++) {
            int i = tid + u * 128;
            int m = i >> 10, c = i & 1023, r = c >> 3, seg = c & 7;
            cp_async16(base + KV_VH + m * 18432 + r * VPITCH + seg * 16,
                       (m ? vl : vh) + (size_t)r * SEQ + seg * 8);
        }
    };

    #pragma unroll
    for (int u = 0; u < 16; u++) {
        int i = tid + u * 128;
        int m = i >> 10, c = i & 1023, r = c >> 4, seg = c & 15;
        const __nv_bfloat16* src = m ? qlp : qhp;
        cp_async16(sb + (m ? AT_QL : AT_QH) + r * QPITCH + seg * 16,
                   src + r * 128 + seg * 8);
    }
    load_kv(0, 0);
    CP_COMMIT();

    float o[16][4];
    #pragma unroll
    for (int n = 0; n < 16; n++)
        #pragma unroll
        for (int e = 0; e < 4; e++) o[n][e] = 0.f;
    float m0 = neg_inf(), m1 = neg_inf(), l0 = 0.f, l1 = 0.f;

    for (int kt = 0; kt <= qt; kt++) {
        int buf = kt & 1;
        if (kt < qt) {
            load_kv(kt + 1, buf ^ 1);
            CP_COMMIT();
            CP_WAIT(1);
        } else {
            CP_WAIT(0);
        }
        __syncthreads();

        uint32_t kvb = sb + AT_K0 + (uint32_t)buf * AT_STAGE;

        float s4[8][4];
        #pragma unroll
        for (int j = 0; j < 8; j++)
            #pragma unroll
            for (int e = 0; e < 4; e++) s4[j][e] = 0.f;
        #pragma unroll
        for (int ks = 0; ks < 8; ks++) {
            uint32_t ah[4], al[4];
            uint32_t qa = (uint32_t)(wm16 + (lane & 15)) * QPITCH
                        + ks * 32 + ((lane >> 4) & 1) * 16;
            LDSM_X4(ah, sb + AT_QH + qa);
            LDSM_X4(al, sb + AT_QL + qa);
            #pragma unroll
            for (int j = 0; j < 8; j++) {
                uint32_t bh[2], bl[2];
                uint32_t ka = (uint32_t)(j * 8 + (lane & 7)) * QPITCH
                            + ks * 32 + ((lane >> 3) & 1) * 16;
                LDSM_X2(bh, kvb + KV_KH + ka);
                LDSM_X2(bl, kvb + KV_KL + ka);
                MMA_BF16(s4[j], ah, bh);
                MMA_BF16(s4[j], al, bh);
                MMA_BF16(s4[j], ah, bl);
            }
        }

        if (kt == qt) {
            int colb = 2 * (lane & 3);
            int rowb = wm16 + (lane >> 2);
            #pragma unroll
            for (int j = 0; j < 8; j++) {
                int c0 = j * 8 + colb;
                if (c0     > rowb)     s4[j][0] = neg_inf();
                if (c0 + 1 > rowb)     s4[j][1] = neg_inf();
                if (c0     > rowb + 8) s4[j][2] = neg_inf();
                if (c0 + 1 > rowb + 8) s4[j][3] = neg_inf();
            }
        }

        float tm0 = neg_inf(), tm1 = neg_inf();
        #pragma unroll
        for (int j = 0; j < 8; j++) {
            tm0 = fmaxf(tm0, fmaxf(s4[j][0], s4[j][1]));
            tm1 = fmaxf(tm1, fmaxf(s4[j][2], s4[j][3]));
        }
        tm0 = fmaxf(tm0, __shfl_xor_sync(0xffffffffu, tm0, 1));
        tm0 = fmaxf(tm0, __shfl_xor_sync(0xffffffffu, tm0, 2));
        tm1 = fmaxf(tm1, __shfl_xor_sync(0xffffffffu, tm1, 1));
        tm1 = fmaxf(tm1, __shfl_xor_sync(0xffffffffu, tm1, 2));
        float mn0 = fmaxf(m0, tm0), mn1 = fmaxf(m1, tm1);
        float a0 = __expf(m0 - mn0), a1 = __expf(m1 - mn1);
        m0 = mn0; m1 = mn1;

        float rs0 = 0.f, rs1 = 0.f;
        uint32_t pah[4][4], pal[4][4];
        #pragma unroll
        for (int j = 0; j < 8; j++) {
            float p0 = __expf(s4[j][0] - mn0), p1 = __expf(s4[j][1] - mn0);
            float p2 = __expf(s4[j][2] - mn1), p3 = __expf(s4[j][3] - mn1);
            rs0 += p0 + p1; rs1 += p2 + p3;
            __nv_bfloat16 b0 = __float2bfloat16(p0), b1 = __float2bfloat16(p1);
            __nv_bfloat16 b2 = __float2bfloat16(p2), b3 = __float2bfloat16(p3);
            uint32_t h01 = ((uint32_t)__bfloat16_as_ushort(b1) << 16) | __bfloat16_as_ushort(b0);
            uint32_t h23 = ((uint32_t)__bfloat16_as_ushort(b3) << 16) | __bfloat16_as_ushort(b2);
            __nv_bfloat16 c0 = __float2bfloat16(p0 - __bfloat162float(b0));
            __nv_bfloat16 c1 = __float2bfloat16(p1 - __bfloat162float(b1));
            __nv_bfloat16 c2 = __float2bfloat16(p2 - __bfloat162float(b2));
            __nv_bfloat16 c3 = __float2bfloat16(p3 - __bfloat162float(b3));
            uint32_t l01 = ((uint32_t)__bfloat16_as_ushort(c1) << 16) | __bfloat16_as_ushort(c0);
            uint32_t l23 = ((uint32_t)__bfloat16_as_ushort(c3) << 16) | __bfloat16_as_ushort(c2);
            int k2 = j >> 1, odd = (j & 1) << 1;
            pah[k2][odd] = h01; pah[k2][odd + 1] = h23;
            pal[k2][odd] = l01; pal[k2][odd + 1] = l23;
        }
        rs0 += __shfl_xor_sync(0xffffffffu, rs0, 1);
        rs0 += __shfl_xor_sync(0xffffffffu, rs0, 2);
        rs1 += __shfl_xor_sync(0xffffffffu, rs1, 1);
        rs1 += __shfl_xor_sync(0xffffffffu, rs1, 2);
        l0 = l0 * a0 + rs0;
        l1 = l1 * a1 + rs1;
        #pragma unroll
        for (int n = 0; n < 16; n++) {
            o[n][0] *= a0; o[n][1] *= a0; o[n][2] *= a1; o[n][3] *= a1;
        }

        #pragma unroll
        for (int ks2 = 0; ks2 < 4; ks2++) {
            #pragma unroll
            for (int n = 0; n < 16; n++) {
                uint32_t vh[2], vl[2];
                uint32_t va = (uint32_t)(n * 8 + (lane & 7)) * VPITCH
                            + ks2 * 32 + ((lane >> 3) & 1) * 16;
                LDSM_X2(vh, kvb + KV_VH + va);
                LDSM_X2(vl, kvb + KV_VL + va);
                MMA_BF16(o[n], pah[ks2], vh);
                MMA_BF16(o[n], pal[ks2], vh);
                MMA_BF16(o[n], pah[ks2], vl);
            }
        }
        __syncthreads();
    }

    float inv0 = 1.f / l0, inv1 = 1.f / l1;
    int rg = qt * 64 + wm16 + (lane >> 2);
    int cb = h * 128 + 2 * (lane & 3);
    #pragma unroll
    for (int n = 0; n < 16; n++) {
        float* p0 = out + (size_t)rg * HID + cb + n * 8;
        *(float2*)p0 = make_float2(o[n][0] * inv0, o[n][1] * inv0);
        float* p1 = out + (size_t)(rg + 8) * HID + cb + n * 8;
        *(float2*)p1 = make_float2(o[n][2] * inv1, o[n][3] * inv1);
    }
}

extern "C" void kernel_launch(void* const* d_in, const int* in_sizes, int n_in,
                              void* d_out, int out_size) {
    const float* hidden = (const float*)d_in[0];
    const int*   pos    = (const int*)d_in[1];
    const int*   qkv_qw = (const int*)d_in[2];
    const float* qkv_s  = (const float*)d_in[3];
    const float* qkv_z  = (const float*)d_in[4];
    const int*   o_qw   = (const int*)d_in[5];
    const float* o_s    = (const float*)d_in[6];
    const float* o_z    = (const float*)d_in[7];
    float* out = (float*)d_out;

    void* p;
    cudaGetSymbolAddress(&p, g_proj); float* proj = (float*)p;
    cudaGetSymbolAddress(&p, g_attn); float* attn = (float*)p;
    cudaGetSymbolAddress(&p, g_R);    float* R    = (float*)p;
    cudaGetSymbolAddress(&p, g_ah);   __half* ah  = (__half*)p;
    cudaGetSymbolAddress(&p, g_al);   __half* al  = (__half*)p;
    cudaGetSymbolAddress(&p, g_bq);   __half* bq  = (__half*)p;

    int gemm_smem = 3 * GSTAGE;                       // 98304
    cudaFuncSetAttribute(gemm_q_kernel,
                         cudaFuncAttributeMaxDynamicSharedMemorySize, gemm_smem);
    cudaFuncSetAttribute(attn_mma_kernel,
                         cudaFuncAttributeMaxDynamicSharedMemorySize, AT_SMEM);

    // 1. RoPE tables
    rope_tables_kernel<<<SEQ, 64>>>(pos);

    // 2. prep: fused split+rowsums, exact-q weights, scales (QKV)
    split_rowsum_kernel<<<SEQ, 256>>>(hidden, ah, al);
    qT_kernel<<<dim3(QKVN / 64, HID / 64), 256>>>(qkv_qw, bq, QKVN);
    prep_scales_kernel<<<QKVN / 32, 256>>>(qkv_s, qkv_z, R, bq, QKVN);

    // 3. QKV projection (exact-q GEMM)
    gemm_q_kernel<<<dim3(SEQ / 128, QKVN / 256), 256, gemm_smem>>>(
        ah, al, bq, R, proj, SEQ, QKVN);

    // 4. RoPE + split Q/K; transpose + split V
    rope_split_kernel<<<SEQ, 256>>>();
    v_transpose_split_kernel<<<dim3(SEQ / 32, HDIM / 32, HEADS), dim3(32, 8)>>>();

    // 5. causal flash attention
    attn_mma_kernel<<<dim3(HEADS, SEQ / 64), 128, AT_SMEM>>>(attn);

    // 6. prep for O projection
    split_rowsum_kernel<<<SEQ, 256>>>(attn, ah, al);
    qT_kernel<<<dim3(HID / 64, HID / 64), 256>>>(o_qw, bq, HID);
    prep_scales_kernel<<<HID / 32, 256>>>(o_s, o_z, R, bq, HID);

    // 7. output projection
    gemm_q_kernel<<<dim3(SEQ / 128, HID / 256), 256, gemm_smem>>>(
        ah, al, bq, R, out, SEQ, HID);
}

// round 12
// speedup vs baseline: 1.0485x; 1.0485x over previous
#include <cuda_runtime.h>
#include <cuda_bf16.h>
#include <cuda_fp16.h>
#include <math.h>
#include <stdint.h>

#define SEQ   2048
#define HID   4096
#define HEADS 32
#define HDIM  128
#define QKVN  12288
#define KPAD  4160          // 4096 + 64 ext cols (zero-correction)
#define NCH   130           // KPAD / 32

// ---------------- scratch (device globals; no runtime allocation) ----------------
__device__ float g_proj[(size_t)SEQ * QKVN];
__device__ float g_attn[(size_t)SEQ * HID];
__device__ float g_cos[SEQ * 64];
__device__ float g_sin[SEQ * 64];
__device__ float g_R[(size_t)32 * QKVN];                      // telescoping ratios
__device__ __half g_ah[(size_t)SEQ * KPAD];                   // activation hi (fp16)
__device__ __half g_al[(size_t)SEQ * KPAD];                   // activation lo
__device__ __half g_bq[(size_t)QKVN * KPAD];                  // exact q^T + ext cols
__device__ __nv_bfloat16 g_qh[(size_t)HEADS * SEQ * HDIM];
__device__ __nv_bfloat16 g_ql[(size_t)HEADS * SEQ * HDIM];
__device__ __nv_bfloat16 g_kh[(size_t)HEADS * SEQ * HDIM];
__device__ __nv_bfloat16 g_kl[(size_t)HEADS * SEQ * HDIM];
__device__ __nv_bfloat16 g_vth[(size_t)HEADS * HDIM * SEQ];
__device__ __nv_bfloat16 g_vtl[(size_t)HEADS * HDIM * SEQ];

__device__ __forceinline__ float neg_inf() { return __int_as_float(0xff800000); }

__device__ __forceinline__ uint32_t smem_to_u32(const void* p) {
    uint32_t a;
    asm("{ .reg .u64 t; cvta.to.shared.u64 t, %1; cvt.u32.u64 %0, t; }" : "=r"(a) : "l"(p));
    return a;
}
__device__ __forceinline__ void cp_async16(uint32_t dst, const void* src) {
    asm volatile("cp.async.cg.shared.global [%0], [%1], 16;" :: "r"(dst), "l"(src));
}
#define CP_COMMIT() asm volatile("cp.async.commit_group;" ::: "memory")
#define CP_WAIT(n)  asm volatile("cp.async.wait_group %0;" :: "n"(n) : "memory")

#define LDSM_X4(r, a) \
    asm volatile("ldmatrix.sync.aligned.m8n8.x4.shared.b16 {%0,%1,%2,%3}, [%4];" \
        : "=r"((r)[0]), "=r"((r)[1]), "=r"((r)[2]), "=r"((r)[3]) : "r"(a))
#define LDSM_X2(r, a) \
    asm volatile("ldmatrix.sync.aligned.m8n8.x2.shared.b16 {%0,%1}, [%2];" \
        : "=r"((r)[0]), "=r"((r)[1]) : "r"(a))
#define MMA_BF16(d, a, b) \
    asm volatile("mma.sync.aligned.m16n8k16.row.col.f32.bf16.bf16.f32 " \
        "{%0,%1,%2,%3}, {%4,%5,%6,%7}, {%8,%9}, {%0,%1,%2,%3};" \
        : "+f"((d)[0]), "+f"((d)[1]), "+f"((d)[2]), "+f"((d)[3]) \
        : "r"((a)[0]), "r"((a)[1]), "r"((a)[2]), "r"((a)[3]), "r"((b)[0]), "r"((b)[1]))
#define MMA_F16(d, a, b) \
    asm volatile("mma.sync.aligned.m16n8k16.row.col.f32.f16.f16.f32 " \
        "{%0,%1,%2,%3}, {%4,%5,%6,%7}, {%8,%9}, {%0,%1,%2,%3};" \
        : "+f"((d)[0]), "+f"((d)[1]), "+f"((d)[2]), "+f"((d)[3]) \
        : "r"((a)[0]), "r"((a)[1]), "r"((a)[2]), "r"((a)[3]), "r"((b)[0]), "r"((b)[1]))

__device__ __forceinline__ uint32_t swz(int r, int kbyte) {
    uint32_t seg = ((uint32_t)(kbyte >> 4)) ^ (((uint32_t)r >> 1) & 3u);
    return (uint32_t)r * 64u + (seg << 4) + (uint32_t)(kbyte & 15);
}

// ---------------- RoPE tables ----------------
__global__ void rope_tables_kernel(const int* __restrict__ pos_ids) {
    int s = blockIdx.x;
    int d = threadIdx.x;
    double inv = pow(10000.0, -(double)(2 * d) / 128.0);
    double ang = (double)pos_ids[s] * inv;
    g_cos[s * 64 + d] = (float)cos(ang);
    g_sin[s * 64 + d] = (float)sin(ang);
}

// ---------------- fp32 -> fp16 hi/lo split into padded [M][KPAD] (R7 exact) -----------
__global__ __launch_bounds__(256)
void split_pad_kernel(const float* __restrict__ X, __half* __restrict__ H,
                      __half* __restrict__ L) {
    int i = (blockIdx.x * 256 + threadIdx.x) * 4;
    int r = i >> 12, c = i & 4095;
    float4 v = *(const float4*)(X + i);
    size_t o = (size_t)r * KPAD + c;
    __half h0 = __float2half_rn(v.x), h1 = __float2half_rn(v.y);
    __half h2 = __float2half_rn(v.z), h3 = __float2half_rn(v.w);
    H[o + 0] = h0; H[o + 1] = h1; H[o + 2] = h2; H[o + 3] = h3;
    L[o + 0] = __float2half_rn(v.x - __half2float(h0));
    L[o + 1] = __float2half_rn(v.y - __half2float(h1));
    L[o + 2] = __float2half_rn(v.z - __half2float(h2));
    L[o + 3] = __float2half_rn(v.w - __half2float(h3));
}

// ---------------- per-row per-group sums -> ext cols of A (R7 exact) ----------------
__global__ __launch_bounds__(256)
void rowsum_ext_kernel(const float* __restrict__ X, __half* __restrict__ H,
                       __half* __restrict__ L) {
    __shared__ float gs[32];
    int m = blockIdx.x;
    const float* row = X + (size_t)m * 4096;
    int g = threadIdx.x >> 3, l8 = threadIdx.x & 7;
    float s = 0.f;
    #pragma unroll
    for (int j = 0; j < 16; j++) s += row[g * 128 + l8 * 16 + j];
    s += __shfl_xor_sync(0xffffffffu, s, 1);
    s += __shfl_xor_sync(0xffffffffu, s, 2);
    s += __shfl_xor_sync(0xffffffffu, s, 4);
    if (l8 == 0) gs[g] = s;
    __syncthreads();
    if (threadIdx.x < 32) {
        float v = gs[threadIdx.x];
        __half h = __float2half_rn(v);
        __half lo = __float2half_rn(v - __half2float(h));
        size_t o = (size_t)m * KPAD + 4096 + threadIdx.x;
        H[o] = h; H[o + 32] = h;
        L[o] = lo; L[o + 32] = lo;
    }
}

// ---------------- q transpose: int32 [K][N] -> exact fp16 [N][KPAD] (R7 exact) --------
__global__ __launch_bounds__(256)
void qT_kernel(const int* __restrict__ Qw, __half* __restrict__ B, int N) {
    __shared__ int w[32][33];
    int n0 = blockIdx.x * 32, k0 = blockIdx.y * 32;
    int tx = threadIdx.x & 31, ty = threadIdx.x >> 5;
    #pragma unroll
    for (int rr = 0; rr < 32; rr += 8)
        w[rr + ty][tx] = Qw[(size_t)(k0 + rr + ty) * N + n0 + tx];
    __syncthreads();
    #pragma unroll
    for (int rr = 0; rr < 32; rr += 8)
        B[(size_t)(n0 + rr + ty) * KPAD + k0 + tx] =
            __float2half_rn((float)w[tx][rr + ty]);
}

// ---------------- scale prep: parallel version (ONLY change vs R7; isolated kernel) ---
__global__ __launch_bounds__(256)
void prep_scales_kernel(const float* __restrict__ S, const float* __restrict__ Z,
                        float* __restrict__ R, __half* __restrict__ B, int N) {
    __shared__ float sp[32][33];
    int nl = threadIdx.x & 31, tg = threadIdx.x >> 5;
    int n = blockIdx.x * 32 + nl;
    #pragma unroll
    for (int j = 0; j < 4; j++) {
        int g = tg * 4 + j;
        float s = S[(size_t)g * N + n];
        float z = Z[(size_t)g * N + n];
        sp[g][nl] = fmaxf(s, 1e-30f);
        float t = -s * z;
        __half th = __float2half_rn(t);
        B[(size_t)n * KPAD + 4096 + g] = th;
        B[(size_t)n * KPAD + 4128 + g] = __float2half_rn(t - __half2float(th));
    }
    __syncthreads();
    #pragma unroll
    for (int j = 0; j < 4; j++) {
        int g = tg * 4 + j;
        R[(size_t)g * N + n] = (g < 31) ? sp[g][nl] / sp[g + 1][nl] : sp[31][nl];
    }
}

// ---------------- exact-q fp16 GEMM with telescoping group rescale (R7 exact) ---------
#define GST_AH 0
#define GST_AL 8192
#define GST_B  16384
#define GSTAGE 32768

__global__ __launch_bounds__(256, 1)
void gemm_q_kernel(const __half* __restrict__ Ah, const __half* __restrict__ Al,
                   const __half* __restrict__ B, const float* __restrict__ R,
                   float* __restrict__ C, int M, int N) {
    extern __shared__ char smraw[];
    const uint32_t sb = smem_to_u32(smraw);
    const int tid = threadIdx.x, lane = tid & 31, wid = tid >> 5;
    const int m0 = blockIdx.x << 7, n0 = blockIdx.y << 8;
    const int wm = (wid & 1) << 6;
    const int wn = (wid >> 1) << 6;

    float acc[4][8][4];
    #pragma unroll
    for (int mi = 0; mi < 4; mi++)
        #pragma unroll
        for (int ni = 0; ni < 8; ni++)
            #pragma unroll
            for (int e = 0; e < 4; e++) acc[mi][ni][e] = 0.f;

    auto load_stage = [&](int buf, int c) {
        uint32_t stage = sb + (uint32_t)buf * GSTAGE;
        int k0 = c << 5;
        #pragma unroll
        for (int u = 0; u < 4; u++) {
            int idx = tid + u * 256;
            int hl = idx >> 9;
            int r = (idx & 511) >> 2, seg = idx & 3;
            const __half* src = hl ? Al : Ah;
            cp_async16(stage + (hl ? GST_AL : GST_AH) + swz(r, seg << 4),
                       src + (size_t)(m0 + r) * KPAD + k0 + seg * 8);
        }
        #pragma unroll
        for (int u = 0; u < 4; u++) {
            int idx = tid + u * 256;
            int r = idx >> 2, seg = idx & 3;
            cp_async16(stage + GST_B + swz(r, seg << 4),
                       B + (size_t)(n0 + r) * KPAD + k0 + seg * 8);
        }
        CP_COMMIT();
    };

    load_stage(0, 0);
    load_stage(1, 1);

    float rv[16];
    int buf = 0;
    for (int i = 0; i < NCH; i++) {
        if (i + 2 < NCH) {
            int nb = buf + 2; if (nb >= 3) nb -= 3;
            load_stage(nb, i + 2);
            CP_WAIT(2);
        } else if (i + 1 < NCH) {
            CP_WAIT(1);
        } else {
            CP_WAIT(0);
        }
        __syncthreads();

        if ((i & 3) == 0 && i < 128) {
            int g = i >> 2;
            #pragma unroll
            for (int j = 0; j < 16; j++)
                rv[j] = __ldg(&R[(size_t)g * N + n0 + wn + (j >> 1) * 8
                                 + (lane & 3) * 2 + (j & 1)]);
        }

        uint32_t stage = sb + (uint32_t)buf * GSTAGE;
        #pragma unroll
        for (int ks = 0; ks < 2; ks++) {
            uint32_t a_h[4][4], a_l[4][4];
            int akb = ks * 32 + ((lane >> 4) & 1) * 16;
            #pragma unroll
            for (int mi = 0; mi < 4; mi++) {
                int row = wm + mi * 16 + (lane & 15);
                uint32_t so = swz(row, akb);
                LDSM_X4(a_h[mi], stage + GST_AH + so);
                LDSM_X4(a_l[mi], stage + GST_AL + so);
            }
            int bkb = ks * 32 + ((lane >> 3) & 1) * 16;
            #pragma unroll
            for (int ni = 0; ni < 8; ni++) {
                uint32_t b[2];
                int row = wn + ni * 8 + (lane & 7);
                LDSM_X2(b, stage + GST_B + swz(row, bkb));
                #pragma unroll
                for (int mi = 0; mi < 4; mi++) {
                    MMA_F16(acc[mi][ni], a_h[mi], b);
                    MMA_F16(acc[mi][ni], a_l[mi], b);
                }
            }
        }

        if ((i & 3) == 3 && i < 128) {
            #pragma unroll
            for (int mi = 0; mi < 4; mi++)
                #pragma unroll
                for (int ni = 0; ni < 8; ni++) {
                    acc[mi][ni][0] *= rv[ni * 2];
                    acc[mi][ni][1] *= rv[ni * 2 + 1];
                    acc[mi][ni][2] *= rv[ni * 2];
                    acc[mi][ni][3] *= rv[ni * 2 + 1];
                }
        }
        __syncthreads();
        if (++buf == 3) buf = 0;
    }

    const int er = m0 + wm + (lane >> 2);
    const int ec = n0 + wn + (lane & 3) * 2;
    #pragma unroll
    for (int mi = 0; mi < 4; mi++) {
        #pragma unroll
        for (int ni = 0; ni < 8; ni++) {
            float* p = C + (size_t)(er + mi * 16) * N + ec + ni * 8;
            *(float2*)p                   = make_float2(acc[mi][ni][0], acc[mi][ni][1]);
            *(float2*)(p + 8 * (size_t)N) = make_float2(acc[mi][ni][2], acc[mi][ni][3]);
        }
    }
}

// ---------------- RoPE + split Q/K -> bf16 hi/lo [h][s][d] (R7 exact) ----------------
__global__ __launch_bounds__(256)
void rope_split_kernel() {
    int s = blockIdx.x;
    const float* row = g_proj + (size_t)s * QKVN;
    for (int it = threadIdx.x; it < 4096; it += 256) {
        int qk = it >> 11;
        int hh = (it >> 6) & 31;
        int d  = it & 63;
        float c = g_cos[s * 64 + d], sn = g_sin[s * 64 + d];
        const float* p = row + qk * HID + hh * 128;
        float x1 = p[d], x2 = p[d + 64];
        float y1 = x1 * c - x2 * sn;
        float y2 = x2 * c + x1 * sn;
        if (qk == 0) { y1 *= 0.08838834764831845f; y2 *= 0.08838834764831845f; }
        __nv_bfloat16* H = qk ? g_kh : g_qh;
        __nv_bfloat16* L = qk ? g_kl : g_ql;
        size_t o = ((size_t)hh * SEQ + s) * 128 + d;
        __nv_bfloat16 h1 = __float2bfloat16(y1), h2 = __float2bfloat16(y2);
        H[o] = h1; H[o + 64] = h2;
        L[o]      = __float2bfloat16(y1 - __bfloat162float(h1));
        L[o + 64] = __float2bfloat16(y2 - __bfloat162float(h2));
    }
}

// ---------------- V transpose + split (R7 exact) ----------------
__global__ void v_transpose_split_kernel() {
    __shared__ float t[32][33];
    int s0 = blockIdx.x * 32, d0 = blockIdx.y * 32, h = blockIdx.z;
    int tx = threadIdx.x, ty = threadIdx.y;
    #pragma unroll
    for (int rr = 0; rr < 32; rr += 8)
        t[rr + ty][tx] = g_proj[(size_t)(s0 + rr + ty) * QKVN + 2 * HID + h * 128 + d0 + tx];
    __syncthreads();
    #pragma unroll
    for (int rr = 0; rr < 32; rr += 8) {
        int d = d0 + rr + ty;
        float v = t[tx][rr + ty];
        __nv_bfloat16 hi = __float2bfloat16(v);
        size_t o = ((size_t)h * 128 + d) * SEQ + s0 + tx;
        g_vth[o] = hi;
        g_vtl[o] = __float2bfloat16(v - __bfloat162float(hi));
    }
}

// ---------------- bf16x3 mma.sync flash attention (R7 exact) ----------------
#define QPITCH 272
#define VPITCH 144
#define AT_QH  0
#define AT_QL  17408
#define AT_K0  34816
#define KV_KH  0
#define KV_KL  17408
#define KV_VH  34816
#define KV_VL  53248
#define AT_STAGE 71680
#define AT_SMEM  (AT_K0 + 2 * AT_STAGE)

__global__ __launch_bounds__(128, 1)
void attn_mma_kernel(float* __restrict__ out) {
    extern __shared__ char smraw[];
    const uint32_t sb = smem_to_u32(smraw);
    const int h  = blockIdx.x;
    const int qt = (int)gridDim.y - 1 - (int)blockIdx.y;
    const int tid = threadIdx.x, lane = tid & 31, warp = tid >> 5;
    const int wm16 = warp << 4;

    const __nv_bfloat16* qhp = g_qh + ((size_t)h * SEQ + qt * 64) * 128;
    const __nv_bfloat16* qlp = g_ql + ((size_t)h * SEQ + qt * 64) * 128;
    const __nv_bfloat16* kh0 = g_kh + (size_t)h * SEQ * 128;
    const __nv_bfloat16* kl0 = g_kl + (size_t)h * SEQ * 128;
    const __nv_bfloat16* vh0 = g_vth + (size_t)h * 128 * SEQ;
    const __nv_bfloat16* vl0 = g_vtl + (size_t)h * 128 * SEQ;

    auto load_kv = [&](int kt_, int buf_) {
        uint32_t base = sb + AT_K0 + (uint32_t)buf_ * AT_STAGE;
        const __nv_bfloat16* kh = kh0 + (size_t)kt_ * 64 * 128;
        const __nv_bfloat16* kl = kl0 + (size_t)kt_ * 64 * 128;
        #pragma unroll
        for (int u = 0; u < 16; u++) {
            int i = tid + u * 128;
            int m = i >> 10, c = i & 1023, r = c >> 4, seg = c & 15;
            cp_async16(base + m * 17408 + r * QPITCH + seg * 16,
                       (m ? kl : kh) + r * 128 + seg * 8);
        }
        const __nv_bfloat16* vh = vh0 + kt_ * 64;
        const __nv_bfloat16* vl = vl0 + kt_ * 64;
        #pragma unroll
        for (int u = 0; u < 16; u++) {
            int i = tid + u * 128;
            int m = i >> 10, c = i & 1023, r = c >> 3, seg = c & 7;
            cp_async16(base + KV_VH + m * 18432 + r * VPITCH + seg * 16,
                       (m ? vl : vh) + (size_t)r * SEQ + seg * 8);
        }
    };

    #pragma unroll
    for (int u = 0; u < 16; u++) {
        int i = tid + u * 128;
        int m = i >> 10, c = i & 1023, r = c >> 4, seg = c & 15;
        const __nv_bfloat16* src = m ? qlp : qhp;
        cp_async16(sb + (m ? AT_QL : AT_QH) + r * QPITCH + seg * 16,
                   src + r * 128 + seg * 8);
    }
    load_kv(0, 0);
    CP_COMMIT();

    float o[16][4];
    #pragma unroll
    for (int n = 0; n < 16; n++)
        #pragma unroll
        for (int e = 0; e < 4; e++) o[n][e] = 0.f;
    float m0 = neg_inf(), m1 = neg_inf(), l0 = 0.f, l1 = 0.f;

    for (int kt = 0; kt <= qt; kt++) {
        int buf = kt & 1;
        if (kt < qt) {
            load_kv(kt + 1, buf ^ 1);
            CP_COMMIT();
            CP_WAIT(1);
        } else {
            CP_WAIT(0);
        }
        __syncthreads();

        uint32_t kvb = sb + AT_K0 + (uint32_t)buf * AT_STAGE;

        float s4[8][4];
        #pragma unroll
        for (int j = 0; j < 8; j++)
            #pragma unroll
            for (int e = 0; e < 4; e++) s4[j][e] = 0.f;
        #pragma unroll
        for (int ks = 0; ks < 8; ks++) {
            uint32_t ah[4], al[4];
            uint32_t qa = (uint32_t)(wm16 + (lane & 15)) * QPITCH
                        + ks * 32 + ((lane >> 4) & 1) * 16;
            LDSM_X4(ah, sb + AT_QH + qa);
            LDSM_X4(al, sb + AT_QL + qa);
            #pragma unroll
            for (int j = 0; j < 8; j++) {
                uint32_t bh[2], bl[2];
                uint32_t ka = (uint32_t)(j * 8 + (lane & 7)) * QPITCH
                            + ks * 32 + ((lane >> 3) & 1) * 16;
                LDSM_X2(bh, kvb + KV_KH + ka);
                LDSM_X2(bl, kvb + KV_KL + ka);
                MMA_BF16(s4[j], ah, bh);
                MMA_BF16(s4[j], al, bh);
                MMA_BF16(s4[j], ah, bl);
            }
        }

        if (kt == qt) {
            int colb = 2 * (lane & 3);
            int rowb = wm16 + (lane >> 2);
            #pragma unroll
            for (int j = 0; j < 8; j++) {
                int c0 = j * 8 + colb;
                if (c0     > rowb)     s4[j][0] = neg_inf();
                if (c0 + 1 > rowb)     s4[j][1] = neg_inf();
                if (c0     > rowb + 8) s4[j][2] = neg_inf();
                if (c0 + 1 > rowb + 8) s4[j][3] = neg_inf();
            }
        }

        float tm0 = neg_inf(), tm1 = neg_inf();
        #pragma unroll
        for (int j = 0; j < 8; j++) {
            tm0 = fmaxf(tm0, fmaxf(s4[j][0], s4[j][1]));
            tm1 = fmaxf(tm1, fmaxf(s4[j][2], s4[j][3]));
        }
        tm0 = fmaxf(tm0, __shfl_xor_sync(0xffffffffu, tm0, 1));
        tm0 = fmaxf(tm0, __shfl_xor_sync(0xffffffffu, tm0, 2));
        tm1 = fmaxf(tm1, __shfl_xor_sync(0xffffffffu, tm1, 1));
        tm1 = fmaxf(tm1, __shfl_xor_sync(0xffffffffu, tm1, 2));
        float mn0 = fmaxf(m0, tm0), mn1 = fmaxf(m1, tm1);
        float a0 = __expf(m0 - mn0), a1 = __expf(m1 - mn1);
        m0 = mn0; m1 = mn1;

        float rs0 = 0.f, rs1 = 0.f;
        uint32_t pah[4][4], pal[4][4];
        #pragma unroll
        for (int j = 0; j < 8; j++) {
            float p0 = __expf(s4[j][0] - mn0), p1 = __expf(s4[j][1] - mn0);
            float p2 = __expf(s4[j][2] - mn1), p3 = __expf(s4[j][3] - mn1);
            rs0 += p0 + p1; rs1 += p2 + p3;
            __nv_bfloat16 b0 = __float2bfloat16(p0), b1 = __float2bfloat16(p1);
            __nv_bfloat16 b2 = __float2bfloat16(p2), b3 = __float2bfloat16(p3);
            uint32_t h01 = ((uint32_t)__bfloat16_as_ushort(b1) << 16) | __bfloat16_as_ushort(b0);
            uint32_t h23 = ((uint32_t)__bfloat16_as_ushort(b3) << 16) | __bfloat16_as_ushort(b2);
            __nv_bfloat16 c0 = __float2bfloat16(p0 - __bfloat162float(b0));
            __nv_bfloat16 c1 = __float2bfloat16(p1 - __bfloat162float(b1));
            __nv_bfloat16 c2 = __float2bfloat16(p2 - __bfloat162float(b2));
            __nv_bfloat16 c3 = __float2bfloat16(p3 - __bfloat162float(b3));
            uint32_t l01 = ((uint32_t)__bfloat16_as_ushort(c1) << 16) | __bfloat16_as_ushort(c0);
            uint32_t l23 = ((uint32_t)__bfloat16_as_ushort(c3) << 16) | __bfloat16_as_ushort(c2);
            int k2 = j >> 1, odd = (j & 1) << 1;
            pah[k2][odd] = h01; pah[k2][odd + 1] = h23;
            pal[k2][odd] = l01; pal[k2][odd + 1] = l23;
        }
        rs0 += __shfl_xor_sync(0xffffffffu, rs0, 1);
        rs0 += __shfl_xor_sync(0xffffffffu, rs0, 2);
        rs1 += __shfl_xor_sync(0xffffffffu, rs1, 1);
        rs1 += __shfl_xor_sync(0xffffffffu, rs1, 2);
        l0 = l0 * a0 + rs0;
        l1 = l1 * a1 + rs1;
        #pragma unroll
        for (int n = 0; n < 16; n++) {
            o[n][0] *= a0; o[n][1] *= a0; o[n][2] *= a1; o[n][3] *= a1;
        }

        #pragma unroll
        for (int ks2 = 0; ks2 < 4; ks2++) {
            #pragma unroll
            for (int n = 0; n < 16; n++) {
                uint32_t vh[2], vl[2];
                uint32_t va = (uint32_t)(n * 8 + (lane & 7)) * VPITCH
                            + ks2 * 32 + ((lane >> 3) & 1) * 16;
                LDSM_X2(vh, kvb + KV_VH + va);
                LDSM_X2(vl, kvb + KV_VL + va);
                MMA_BF16(o[n], pah[ks2], vh);
                MMA_BF16(o[n], pal[ks2], vh);
                MMA_BF16(o[n], pah[ks2], vl);
            }
        }
        __syncthreads();
    }

    float inv0 = 1.f / l0, inv1 = 1.f / l1;
    int rg = qt * 64 + wm16 + (lane >> 2);
    int cb = h * 128 + 2 * (lane & 3);
    #pragma unroll
    for (int n = 0; n < 16; n++) {
        float* p0 = out + (size_t)rg * HID + cb + n * 8;
        *(float2*)p0 = make_float2(o[n][0] * inv0, o[n][1] * inv0);
        float* p1 = out + (size_t)(rg + 8) * HID + cb + n * 8;
        *(float2*)p1 = make_float2(o[n][2] * inv1, o[n][3] * inv1);
    }
}

extern "C" void kernel_launch(void* const* d_in, const int* in_sizes, int n_in,
                              void* d_out, int out_size) {
    const float* hidden = (const float*)d_in[0];
    const int*   pos    = (const int*)d_in[1];
    const int*   qkv_qw = (const int*)d_in[2];
    const float* qkv_s  = (const float*)d_in[3];
    const float* qkv_z  = (const float*)d_in[4];
    const int*   o_qw   = (const int*)d_in[5];
    const float* o_s    = (const float*)d_in[6];
    const float* o_z    = (const float*)d_in[7];
    float* out = (float*)d_out;

    void* p;
    cudaGetSymbolAddress(&p, g_proj); float* proj = (float*)p;
    cudaGetSymbolAddress(&p, g_attn); float* attn = (float*)p;
    cudaGetSymbolAddress(&p, g_R);    float* R    = (float*)p;
    cudaGetSymbolAddress(&p, g_ah);   __half* ah  = (__half*)p;
    cudaGetSymbolAddress(&p, g_al);   __half* al  = (__half*)p;
    cudaGetSymbolAddress(&p, g_bq);   __half* bq  = (__half*)p;

    int gemm_smem = 3 * GSTAGE;                       // 98304
    cudaFuncSetAttribute(gemm_q_kernel,
                         cudaFuncAttributeMaxDynamicSharedMemorySize, gemm_smem);
    cudaFuncSetAttribute(attn_mma_kernel,
                         cudaFuncAttributeMaxDynamicSharedMemorySize, AT_SMEM);

    // 1. RoPE tables
    rope_tables_kernel<<<SEQ, 64>>>(pos);

    // 2. prep: activations (hi/lo + group rowsums), exact-q weights, scales
    split_pad_kernel<<<(SEQ * HID) / (256 * 4), 256>>>(hidden, ah, al);
    rowsum_ext_kernel<<<SEQ, 256>>>(hidden, ah, al);
    qT_kernel<<<dim3(QKVN / 32, HID / 32), 256>>>(qkv_qw, bq, QKVN);
    prep_scales_kernel<<<QKVN / 32, 256>>>(qkv_s, qkv_z, R, bq, QKVN);

    // 3. QKV projection (exact-q GEMM)
    gemm_q_kernel<<<dim3(SEQ / 128, QKVN / 256), 256, gemm_smem>>>(
        ah, al, bq, R, proj, SEQ, QKVN);

    // 4. RoPE + split Q/K; transpose + split V
    rope_split_kernel<<<SEQ, 256>>>();
    v_transpose_split_kernel<<<dim3(SEQ / 32, HDIM / 32, HEADS), dim3(32, 8)>>>();

    // 5. causal flash attention
    attn_mma_kernel<<<dim3(HEADS, SEQ / 64), 128, AT_SMEM>>>(attn);

    // 6. prep for O projection (reuse ah/al/bq/R)
    split_pad_kernel<<<(SEQ * HID) / (256 * 4), 256>>>(attn, ah, al);
    rowsum_ext_kernel<<<SEQ, 256>>>(attn, ah, al);
    qT_kernel<<<dim3(HID / 32, HID / 32), 256>>>(o_qw, bq, HID);
    prep_scales_kernel<<<HID / 32, 256>>>(o_s, o_z, R, bq, HID);

    // 7. output projection
    gemm_q_kernel<<<dim3(SEQ / 128, HID / 256), 256, gemm_smem>>>(
        ah, al, bq, R, out, SEQ, HID);
}

// round 13
// speedup vs baseline: 1.0599x; 1.0109x over previous
#include <cuda_runtime.h>
#include <cuda_bf16.h>
#include <cuda_fp16.h>
#include <math.h>
#include <stdint.h>

#define SEQ   2048
#define HID   4096
#define HEADS 32
#define HDIM  128
#define QKVN  12288
#define KPAD  4160          // 4096 + 64 ext cols (zero-correction)
#define NCH   130           // KPAD / 32

// ---------------- scratch (device globals; no runtime allocation) ----------------
__device__ float g_proj[(size_t)SEQ * QKVN];
__device__ float g_attn[(size_t)SEQ * HID];
__device__ float g_cos[SEQ * 64];
__device__ float g_sin[SEQ * 64];
__device__ float g_R[(size_t)32 * QKVN];                      // telescoping ratios
__device__ __half g_ah[(size_t)SEQ * KPAD];                   // activation hi (fp16)
__device__ __half g_al[(size_t)SEQ * KPAD];                   // activation lo
__device__ __half g_bq[(size_t)QKVN * KPAD];                  // exact q^T + ext cols
__device__ __nv_bfloat16 g_qh[(size_t)HEADS * SEQ * HDIM];
__device__ __nv_bfloat16 g_ql[(size_t)HEADS * SEQ * HDIM];
__device__ __nv_bfloat16 g_kh[(size_t)HEADS * SEQ * HDIM];
__device__ __nv_bfloat16 g_kl[(size_t)HEADS * SEQ * HDIM];
__device__ __nv_bfloat16 g_vth[(size_t)HEADS * HDIM * SEQ];
__device__ __nv_bfloat16 g_vtl[(size_t)HEADS * HDIM * SEQ];

__device__ __forceinline__ float neg_inf() { return __int_as_float(0xff800000); }

__device__ __forceinline__ uint32_t smem_to_u32(const void* p) {
    uint32_t a;
    asm("{ .reg .u64 t; cvta.to.shared.u64 t, %1; cvt.u32.u64 %0, t; }" : "=r"(a) : "l"(p));
    return a;
}
__device__ __forceinline__ void cp_async16(uint32_t dst, const void* src) {
    asm volatile("cp.async.cg.shared.global [%0], [%1], 16;" :: "r"(dst), "l"(src));
}
#define CP_COMMIT() asm volatile("cp.async.commit_group;" ::: "memory")
#define CP_WAIT(n)  asm volatile("cp.async.wait_group %0;" :: "n"(n) : "memory")

#define LDSM_X4(r, a) \
    asm volatile("ldmatrix.sync.aligned.m8n8.x4.shared.b16 {%0,%1,%2,%3}, [%4];" \
        : "=r"((r)[0]), "=r"((r)[1]), "=r"((r)[2]), "=r"((r)[3]) : "r"(a))
#define LDSM_X2(r, a) \
    asm volatile("ldmatrix.sync.aligned.m8n8.x2.shared.b16 {%0,%1}, [%2];" \
        : "=r"((r)[0]), "=r"((r)[1]) : "r"(a))
#define MMA_BF16(d, a, b) \
    asm volatile("mma.sync.aligned.m16n8k16.row.col.f32.bf16.bf16.f32 " \
        "{%0,%1,%2,%3}, {%4,%5,%6,%7}, {%8,%9}, {%0,%1,%2,%3};" \
        : "+f"((d)[0]), "+f"((d)[1]), "+f"((d)[2]), "+f"((d)[3]) \
        : "r"((a)[0]), "r"((a)[1]), "r"((a)[2]), "r"((a)[3]), "r"((b)[0]), "r"((b)[1]))
#define MMA_F16(d, a, b) \
    asm volatile("mma.sync.aligned.m16n8k16.row.col.f32.f16.f16.f32 " \
        "{%0,%1,%2,%3}, {%4,%5,%6,%7}, {%8,%9}, {%0,%1,%2,%3};" \
        : "+f"((d)[0]), "+f"((d)[1]), "+f"((d)[2]), "+f"((d)[3]) \
        : "r"((a)[0]), "r"((a)[1]), "r"((a)[2]), "r"((a)[3]), "r"((b)[0]), "r"((b)[1]))

__device__ __forceinline__ uint32_t swz(int r, int kbyte) {
    uint32_t seg = ((uint32_t)(kbyte >> 4)) ^ (((uint32_t)r >> 1) & 3u);
    return (uint32_t)r * 64u + (seg << 4) + (uint32_t)(kbyte & 15);
}

// ---------------- RoPE tables ----------------
__global__ void rope_tables_kernel(const int* __restrict__ pos_ids) {
    int s = blockIdx.x;
    int d = threadIdx.x;
    double inv = pow(10000.0, -(double)(2 * d) / 128.0);
    double ang = (double)pos_ids[s] * inv;
    g_cos[s * 64 + d] = (float)cos(ang);
    g_sin[s * 64 + d] = (float)sin(ang);
}

// ---------------- fp32 -> fp16 hi/lo split into padded [M][KPAD] (R12 exact) ----------
__global__ __launch_bounds__(256)
void split_pad_kernel(const float* __restrict__ X, __half* __restrict__ H,
                      __half* __restrict__ L) {
    int i = (blockIdx.x * 256 + threadIdx.x) * 4;
    int r = i >> 12, c = i & 4095;
    float4 v = *(const float4*)(X + i);
    size_t o = (size_t)r * KPAD + c;
    __half h0 = __float2half_rn(v.x), h1 = __float2half_rn(v.y);
    __half h2 = __float2half_rn(v.z), h3 = __float2half_rn(v.w);
    H[o + 0] = h0; H[o + 1] = h1; H[o + 2] = h2; H[o + 3] = h3;
    L[o + 0] = __float2half_rn(v.x - __half2float(h0));
    L[o + 1] = __float2half_rn(v.y - __half2float(h1));
    L[o + 2] = __float2half_rn(v.z - __half2float(h2));
    L[o + 3] = __float2half_rn(v.w - __half2float(h3));
}

// ---------------- per-row per-group sums -> ext cols of A (R12 exact) ----------------
__global__ __launch_bounds__(256)
void rowsum_ext_kernel(const float* __restrict__ X, __half* __restrict__ H,
                       __half* __restrict__ L) {
    __shared__ float gs[32];
    int m = blockIdx.x;
    const float* row = X + (size_t)m * 4096;
    int g = threadIdx.x >> 3, l8 = threadIdx.x & 7;
    float s = 0.f;
    #pragma unroll
    for (int j = 0; j < 16; j++) s += row[g * 128 + l8 * 16 + j];
    s += __shfl_xor_sync(0xffffffffu, s, 1);
    s += __shfl_xor_sync(0xffffffffu, s, 2);
    s += __shfl_xor_sync(0xffffffffu, s, 4);
    if (l8 == 0) gs[g] = s;
    __syncthreads();
    if (threadIdx.x < 32) {
        float v = gs[threadIdx.x];
        __half h = __float2half_rn(v);
        __half lo = __float2half_rn(v - __half2float(h));
        size_t o = (size_t)m * KPAD + 4096 + threadIdx.x;
        H[o] = h; H[o + 32] = h;
        L[o] = lo; L[o + 32] = lo;
    }
}

// ---------------- q transpose: coalesced 64x64 tile (ONLY change vs R12) --------------
// reads int4 (coalesced), writes uint4 = 8 halves along k (coalesced within row)
__global__ __launch_bounds__(256)
void qT_kernel(const int* __restrict__ Qw, __half* __restrict__ B, int N) {
    __shared__ int w[64][65];
    int n0 = blockIdx.x * 64, k0 = blockIdx.y * 64;
    int tid = threadIdx.x;
    int tx = tid & 15, ty = tid >> 4;           // 16 int4 per row, 16 rows per pass
    #pragma unroll
    for (int p = 0; p < 4; p++) {
        int r = p * 16 + ty;
        int4 v = *(const int4*)(Qw + (size_t)(k0 + r) * N + n0 + tx * 4);
        w[r][tx * 4 + 0] = v.x; w[r][tx * 4 + 1] = v.y;
        w[r][tx * 4 + 2] = v.z; w[r][tx * 4 + 3] = v.w;
    }
    __syncthreads();
    int kx = tid & 7, ny = tid >> 3;            // 8 x uint4(8 half) per n-row
    #pragma unroll
    for (int p = 0; p < 2; p++) {
        int n = p * 32 + ny;
        __half h[8];
        #pragma unroll
        for (int j = 0; j < 8; j++) h[j] = __float2half_rn((float)w[kx * 8 + j][n]);
        *(uint4*)(B + (size_t)(n0 + n) * KPAD + k0 + kx * 8) = *(uint4*)h;
    }
}

// ---------------- scale prep: parallel (validated R12) ----------------
__global__ __launch_bounds__(256)
void prep_scales_kernel(const float* __restrict__ S, const float* __restrict__ Z,
                        float* __restrict__ R, __half* __restrict__ B, int N) {
    __shared__ float sp[32][33];
    int nl = threadIdx.x & 31, tg = threadIdx.x >> 5;
    int n = blockIdx.x * 32 + nl;
    #pragma unroll
    for (int j = 0; j < 4; j++) {
        int g = tg * 4 + j;
        float s = S[(size_t)g * N + n];
        float z = Z[(size_t)g * N + n];
        sp[g][nl] = fmaxf(s, 1e-30f);
        float t = -s * z;
        __half th = __float2half_rn(t);
        B[(size_t)n * KPAD + 4096 + g] = th;
        B[(size_t)n * KPAD + 4128 + g] = __float2half_rn(t - __half2float(th));
    }
    __syncthreads();
    #pragma unroll
    for (int j = 0; j < 4; j++) {
        int g = tg * 4 + j;
        R[(size_t)g * N + n] = (g < 31) ? sp[g][nl] / sp[g + 1][nl] : sp[31][nl];
    }
}

// ---------------- exact-q fp16 GEMM with telescoping group rescale (R12 exact) --------
#define GST_AH 0
#define GST_AL 8192
#define GST_B  16384
#define GSTAGE 32768

__global__ __launch_bounds__(256, 1)
void gemm_q_kernel(const __half* __restrict__ Ah, const __half* __restrict__ Al,
                   const __half* __restrict__ B, const float* __restrict__ R,
                   float* __restrict__ C, int M, int N) {
    extern __shared__ char smraw[];
    const uint32_t sb = smem_to_u32(smraw);
    const int tid = threadIdx.x, lane = tid & 31, wid = tid >> 5;
    const int m0 = blockIdx.x << 7, n0 = blockIdx.y << 8;
    const int wm = (wid & 1) << 6;
    const int wn = (wid >> 1) << 6;

    float acc[4][8][4];
    #pragma unroll
    for (int mi = 0; mi < 4; mi++)
        #pragma unroll
        for (int ni = 0; ni < 8; ni++)
            #pragma unroll
            for (int e = 0; e < 4; e++) acc[mi][ni][e] = 0.f;

    auto load_stage = [&](int buf, int c) {
        uint32_t stage = sb + (uint32_t)buf * GSTAGE;
        int k0 = c << 5;
        #pragma unroll
        for (int u = 0; u < 4; u++) {
            int idx = tid + u * 256;
            int hl = idx >> 9;
            int r = (idx & 511) >> 2, seg = idx & 3;
            const __half* src = hl ? Al : Ah;
            cp_async16(stage + (hl ? GST_AL : GST_AH) + swz(r, seg << 4),
                       src + (size_t)(m0 + r) * KPAD + k0 + seg * 8);
        }
        #pragma unroll
        for (int u = 0; u < 4; u++) {
            int idx = tid + u * 256;
            int r = idx >> 2, seg = idx & 3;
            cp_async16(stage + GST_B + swz(r, seg << 4),
                       B + (size_t)(n0 + r) * KPAD + k0 + seg * 8);
        }
        CP_COMMIT();
    };

    load_stage(0, 0);
    load_stage(1, 1);

    float rv[16];
    int buf = 0;
    for (int i = 0; i < NCH; i++) {
        if (i + 2 < NCH) {
            int nb = buf + 2; if (nb >= 3) nb -= 3;
            load_stage(nb, i + 2);
            CP_WAIT(2);
        } else if (i + 1 < NCH) {
            CP_WAIT(1);
        } else {
            CP_WAIT(0);
        }
        __syncthreads();

        if ((i & 3) == 0 && i < 128) {
            int g = i >> 2;
            #pragma unroll
            for (int j = 0; j < 16; j++)
                rv[j] = __ldg(&R[(size_t)g * N + n0 + wn + (j >> 1) * 8
                                 + (lane & 3) * 2 + (j & 1)]);
        }

        uint32_t stage = sb + (uint32_t)buf * GSTAGE;
        #pragma unroll
        for (int ks = 0; ks < 2; ks++) {
            uint32_t a_h[4][4], a_l[4][4];
            int akb = ks * 32 + ((lane >> 4) & 1) * 16;
            #pragma unroll
            for (int mi = 0; mi < 4; mi++) {
                int row = wm + mi * 16 + (lane & 15);
                uint32_t so = swz(row, akb);
                LDSM_X4(a_h[mi], stage + GST_AH + so);
                LDSM_X4(a_l[mi], stage + GST_AL + so);
            }
            int bkb = ks * 32 + ((lane >> 3) & 1) * 16;
            #pragma unroll
            for (int ni = 0; ni < 8; ni++) {
                uint32_t b[2];
                int row = wn + ni * 8 + (lane & 7);
                LDSM_X2(b, stage + GST_B + swz(row, bkb));
                #pragma unroll
                for (int mi = 0; mi < 4; mi++) {
                    MMA_F16(acc[mi][ni], a_h[mi], b);
                    MMA_F16(acc[mi][ni], a_l[mi], b);
                }
            }
        }

        if ((i & 3) == 3 && i < 128) {
            #pragma unroll
            for (int mi = 0; mi < 4; mi++)
                #pragma unroll
                for (int ni = 0; ni < 8; ni++) {
                    acc[mi][ni][0] *= rv[ni * 2];
                    acc[mi][ni][1] *= rv[ni * 2 + 1];
                    acc[mi][ni][2] *= rv[ni * 2];
                    acc[mi][ni][3] *= rv[ni * 2 + 1];
                }
        }
        __syncthreads();
        if (++buf == 3) buf = 0;
    }

    const int er = m0 + wm + (lane >> 2);
    const int ec = n0 + wn + (lane & 3) * 2;
    #pragma unroll
    for (int mi = 0; mi < 4; mi++) {
        #pragma unroll
        for (int ni = 0; ni < 8; ni++) {
            float* p = C + (size_t)(er + mi * 16) * N + ec + ni * 8;
            *(float2*)p                   = make_float2(acc[mi][ni][0], acc[mi][ni][1]);
            *(float2*)(p + 8 * (size_t)N) = make_float2(acc[mi][ni][2], acc[mi][ni][3]);
        }
    }
}

// ---------------- RoPE + split Q/K -> bf16 hi/lo [h][s][d] (R12 exact) ----------------
__global__ __launch_bounds__(256)
void rope_split_kernel() {
    int s = blockIdx.x;
    const float* row = g_proj + (size_t)s * QKVN;
    for (int it = threadIdx.x; it < 4096; it += 256) {
        int qk = it >> 11;
        int hh = (it >> 6) & 31;
        int d  = it & 63;
        float c = g_cos[s * 64 + d], sn = g_sin[s * 64 + d];
        const float* p = row + qk * HID + hh * 128;
        float x1 = p[d], x2 = p[d + 64];
        float y1 = x1 * c - x2 * sn;
        float y2 = x2 * c + x1 * sn;
        if (qk == 0) { y1 *= 0.08838834764831845f; y2 *= 0.08838834764831845f; }
        __nv_bfloat16* H = qk ? g_kh : g_qh;
        __nv_bfloat16* L = qk ? g_kl : g_ql;
        size_t o = ((size_t)hh * SEQ + s) * 128 + d;
        __nv_bfloat16 h1 = __float2bfloat16(y1), h2 = __float2bfloat16(y2);
        H[o] = h1; H[o + 64] = h2;
        L[o]      = __float2bfloat16(y1 - __bfloat162float(h1));
        L[o + 64] = __float2bfloat16(y2 - __bfloat162float(h2));
    }
}

// ---------------- V transpose + split (R12 exact) ----------------
__global__ void v_transpose_split_kernel() {
    __shared__ float t[32][33];
    int s0 = blockIdx.x * 32, d0 = blockIdx.y * 32, h = blockIdx.z;
    int tx = threadIdx.x, ty = threadIdx.y;
    #pragma unroll
    for (int rr = 0; rr < 32; rr += 8)
        t[rr + ty][tx] = g_proj[(size_t)(s0 + rr + ty) * QKVN + 2 * HID + h * 128 + d0 + tx];
    __syncthreads();
    #pragma unroll
    for (int rr = 0; rr < 32; rr += 8) {
        int d = d0 + rr + ty;
        float v = t[tx][rr + ty];
        __nv_bfloat16 hi = __float2bfloat16(v);
        size_t o = ((size_t)h * 128 + d) * SEQ + s0 + tx;
        g_vth[o] = hi;
        g_vtl[o] = __float2bfloat16(v - __bfloat162float(hi));
    }
}

// ---------------- bf16x3 mma.sync flash attention (R12 exact) ----------------
#define QPITCH 272
#define VPITCH 144
#define AT_QH  0
#define AT_QL  17408
#define AT_K0  34816
#define KV_KH  0
#define KV_KL  17408
#define KV_VH  34816
#define KV_VL  53248
#define AT_STAGE 71680
#define AT_SMEM  (AT_K0 + 2 * AT_STAGE)

__global__ __launch_bounds__(128, 1)
void attn_mma_kernel(float* __restrict__ out) {
    extern __shared__ char smraw[];
    const uint32_t sb = smem_to_u32(smraw);
    const int h  = blockIdx.x;
    const int qt = (int)gridDim.y - 1 - (int)blockIdx.y;
    const int tid = threadIdx.x, lane = tid & 31, warp = tid >> 5;
    const int wm16 = warp << 4;

    const __nv_bfloat16* qhp = g_qh + ((size_t)h * SEQ + qt * 64) * 128;
    const __nv_bfloat16* qlp = g_ql + ((size_t)h * SEQ + qt * 64) * 128;
    const __nv_bfloat16* kh0 = g_kh + (size_t)h * SEQ * 128;
    const __nv_bfloat16* kl0 = g_kl + (size_t)h * SEQ * 128;
    const __nv_bfloat16* vh0 = g_vth + (size_t)h * 128 * SEQ;
    const __nv_bfloat16* vl0 = g_vtl + (size_t)h * 128 * SEQ;

    auto load_kv = [&](int kt_, int buf_) {
        uint32_t base = sb + AT_K0 + (uint32_t)buf_ * AT_STAGE;
        const __nv_bfloat16* kh = kh0 + (size_t)kt_ * 64 * 128;
        const __nv_bfloat16* kl = kl0 + (size_t)kt_ * 64 * 128;
        #pragma unroll
        for (int u = 0; u < 16; u++) {
            int i = tid + u * 128;
            int m = i >> 10, c = i & 1023, r = c >> 4, seg = c & 15;
            cp_async16(base + m * 17408 + r * QPITCH + seg * 16,
                       (m ? kl : kh) + r * 128 + seg * 8);
        }
        const __nv_bfloat16* vh = vh0 + kt_ * 64;
        const __nv_bfloat16* vl = vl0 + kt_ * 64;
        #pragma unroll
        for (int u = 0; u < 16; u++) {
            int i = tid + u * 128;
            int m = i >> 10, c = i & 1023, r = c >> 3, seg = c & 7;
            cp_async16(base + KV_VH + m * 18432 + r * VPITCH + seg * 16,
                       (m ? vl : vh) + (size_t)r * SEQ + seg * 8);
        }
    };

    #pragma unroll
    for (int u = 0; u < 16; u++) {
        int i = tid + u * 128;
        int m = i >> 10, c = i & 1023, r = c >> 4, seg = c & 15;
        const __nv_bfloat16* src = m ? qlp : qhp;
        cp_async16(sb + (m ? AT_QL : AT_QH) + r * QPITCH + seg * 16,
                   src + r * 128 + seg * 8);
    }
    load_kv(0, 0);
    CP_COMMIT();

    float o[16][4];
    #pragma unroll
    for (int n = 0; n < 16; n++)
        #pragma unroll
        for (int e = 0; e < 4; e++) o[n][e] = 0.f;
    float m0 = neg_inf(), m1 = neg_inf(), l0 = 0.f, l1 = 0.f;

    for (int kt = 0; kt <= qt; kt++) {
        int buf = kt & 1;
        if (kt < qt) {
            load_kv(kt + 1, buf ^ 1);
            CP_COMMIT();
            CP_WAIT(1);
        } else {
            CP_WAIT(0);
        }
        __syncthreads();

        uint32_t kvb = sb + AT_K0 + (uint32_t)buf * AT_STAGE;

        float s4[8][4];
        #pragma unroll
        for (int j = 0; j < 8; j++)
            #pragma unroll
            for (int e = 0; e < 4; e++) s4[j][e] = 0.f;
        #pragma unroll
        for (int ks = 0; ks < 8; ks++) {
            uint32_t ah[4], al[4];
            uint32_t qa = (uint32_t)(wm16 + (lane & 15)) * QPITCH
                        + ks * 32 + ((lane >> 4) & 1) * 16;
            LDSM_X4(ah, sb + AT_QH + qa);
            LDSM_X4(al, sb + AT_QL + qa);
            #pragma unroll
            for (int j = 0; j < 8; j++) {
                uint32_t bh[2], bl[2];
                uint32_t ka = (uint32_t)(j * 8 + (lane & 7)) * QPITCH
                            + ks * 32 + ((lane >> 3) & 1) * 16;
                LDSM_X2(bh, kvb + KV_KH + ka);
                LDSM_X2(bl, kvb + KV_KL + ka);
                MMA_BF16(s4[j], ah, bh);
                MMA_BF16(s4[j], al, bh);
                MMA_BF16(s4[j], ah, bl);
            }
        }

        if (kt == qt) {
            int colb = 2 * (lane & 3);
            int rowb = wm16 + (lane >> 2);
            #pragma unroll
            for (int j = 0; j < 8; j++) {
                int c0 = j * 8 + colb;
                if (c0     > rowb)     s4[j][0] = neg_inf();
                if (c0 + 1 > rowb)     s4[j][1] = neg_inf();
                if (c0     > rowb + 8) s4[j][2] = neg_inf();
                if (c0 + 1 > rowb + 8) s4[j][3] = neg_inf();
            }
        }

        float tm0 = neg_inf(), tm1 = neg_inf();
        #pragma unroll
        for (int j = 0; j < 8; j++) {
            tm0 = fmaxf(tm0, fmaxf(s4[j][0], s4[j][1]));
            tm1 = fmaxf(tm1, fmaxf(s4[j][2], s4[j][3]));
        }
        tm0 = fmaxf(tm0, __shfl_xor_sync(0xffffffffu, tm0, 1));
        tm0 = fmaxf(tm0, __shfl_xor_sync(0xffffffffu, tm0, 2));
        tm1 = fmaxf(tm1, __shfl_xor_sync(0xffffffffu, tm1, 1));
        tm1 = fmaxf(tm1, __shfl_xor_sync(0xffffffffu, tm1, 2));
        float mn0 = fmaxf(m0, tm0), mn1 = fmaxf(m1, tm1);
        float a0 = __expf(m0 - mn0), a1 = __expf(m1 - mn1);
        m0 = mn0; m1 = mn1;

        float rs0 = 0.f, rs1 = 0.f;
        uint32_t pah[4][4], pal[4][4];
        #pragma unroll
        for (int j = 0; j < 8; j++) {
            float p0 = __expf(s4[j][0] - mn0), p1 = __expf(s4[j][1] - mn0);
            float p2 = __expf(s4[j][2] - mn1), p3 = __expf(s4[j][3] - mn1);
            rs0 += p0 + p1; rs1 += p2 + p3;
            __nv_bfloat16 b0 = __float2bfloat16(p0), b1 = __float2bfloat16(p1);
            __nv_bfloat16 b2 = __float2bfloat16(p2), b3 = __float2bfloat16(p3);
            uint32_t h01 = ((uint32_t)__bfloat16_as_ushort(b1) << 16) | __bfloat16_as_ushort(b0);
            uint32_t h23 = ((uint32_t)__bfloat16_as_ushort(b3) << 16) | __bfloat16_as_ushort(b2);
            __nv_bfloat16 c0 = __float2bfloat16(p0 - __bfloat162float(b0));
            __nv_bfloat16 c1 = __float2bfloat16(p1 - __bfloat162float(b1));
            __nv_bfloat16 c2 = __float2bfloat16(p2 - __bfloat162float(b2));
            __nv_bfloat16 c3 = __float2bfloat16(p3 - __bfloat162float(b3));
            uint32_t l01 = ((uint32_t)__bfloat16_as_ushort(c1) << 16) | __bfloat16_as_ushort(c0);
            uint32_t l23 = ((uint32_t)__bfloat16_as_ushort(c3) << 16) | __bfloat16_as_ushort(c2);
            int k2 = j >> 1, odd = (j & 1) << 1;
            pah[k2][odd] = h01; pah[k2][odd + 1] = h23;
            pal[k2][odd] = l01; pal[k2][odd + 1] = l23;
        }
        rs0 += __shfl_xor_sync(0xffffffffu, rs0, 1);
        rs0 += __shfl_xor_sync(0xffffffffu, rs0, 2);
        rs1 += __shfl_xor_sync(0xffffffffu, rs1, 1);
        rs1 += __shfl_xor_sync(0xffffffffu, rs1, 2);
        l0 = l0 * a0 + rs0;
        l1 = l1 * a1 + rs1;
        #pragma unroll
        for (int n = 0; n < 16; n++) {
            o[n][0] *= a0; o[n][1] *= a0; o[n][2] *= a1; o[n][3] *= a1;
        }

        #pragma unroll
        for (int ks2 = 0; ks2 < 4; ks2++) {
            #pragma unroll
            for (int n = 0; n < 16; n++) {
                uint32_t vh[2], vl[2];
                uint32_t va = (uint32_t)(n * 8 + (lane & 7)) * VPITCH
                            + ks2 * 32 + ((lane >> 3) & 1) * 16;
                LDSM_X2(vh, kvb + KV_VH + va);
                LDSM_X2(vl, kvb + KV_VL + va);
                MMA_BF16(o[n], pah[ks2], vh);
                MMA_BF16(o[n], pal[ks2], vh);
                MMA_BF16(o[n], pah[ks2], vl);
            }
        }
        __syncthreads();
    }

    float inv0 = 1.f / l0, inv1 = 1.f / l1;
    int rg = qt * 64 + wm16 + (lane >> 2);
    int cb = h * 128 + 2 * (lane & 3);
    #pragma unroll
    for (int n = 0; n < 16; n++) {
        float* p0 = out + (size_t)rg * HID + cb + n * 8;
        *(float2*)p0 = make_float2(o[n][0] * inv0, o[n][1] * inv0);
        float* p1 = out + (size_t)(rg + 8) * HID + cb + n * 8;
        *(float2*)p1 = make_float2(o[n][2] * inv1, o[n][3] * inv1);
    }
}

extern "C" void kernel_launch(void* const* d_in, const int* in_sizes, int n_in,
                              void* d_out, int out_size) {
    const float* hidden = (const float*)d_in[0];
    const int*   pos    = (const int*)d_in[1];
    const int*   qkv_qw = (const int*)d_in[2];
    const float* qkv_s  = (const float*)d_in[3];
    const float* qkv_z  = (const float*)d_in[4];
    const int*   o_qw   = (const int*)d_in[5];
    const float* o_s    = (const float*)d_in[6];
    const float* o_z    = (const float*)d_in[7];
    float* out = (float*)d_out;

    void* p;
    cudaGetSymbolAddress(&p, g_proj); float* proj = (float*)p;
    cudaGetSymbolAddress(&p, g_attn); float* attn = (float*)p;
    cudaGetSymbolAddress(&p, g_R);    float* R    = (float*)p;
    cudaGetSymbolAddress(&p, g_ah);   __half* ah  = (__half*)p;
    cudaGetSymbolAddress(&p, g_al);   __half* al  = (__half*)p;
    cudaGetSymbolAddress(&p, g_bq);   __half* bq  = (__half*)p;

    int gemm_smem = 3 * GSTAGE;                       // 98304
    cudaFuncSetAttribute(gemm_q_kernel,
                         cudaFuncAttributeMaxDynamicSharedMemorySize, gemm_smem);
    cudaFuncSetAttribute(attn_mma_kernel,
                         cudaFuncAttributeMaxDynamicSharedMemorySize, AT_SMEM);

    // 1. RoPE tables
    rope_tables_kernel<<<SEQ, 64>>>(pos);

    // 2. prep: activations (hi/lo + group rowsums), exact-q weights, scales
    split_pad_kernel<<<(SEQ * HID) / (256 * 4), 256>>>(hidden, ah, al);
    rowsum_ext_kernel<<<SEQ, 256>>>(hidden, ah, al);
    qT_kernel<<<dim3(QKVN / 64, HID / 64), 256>>>(qkv_qw, bq, QKVN);
    prep_scales_kernel<<<QKVN / 32, 256>>>(qkv_s, qkv_z, R, bq, QKVN);

    // 3. QKV projection (exact-q GEMM)
    gemm_q_kernel<<<dim3(SEQ / 128, QKVN / 256), 256, gemm_smem>>>(
        ah, al, bq, R, proj, SEQ, QKVN);

    // 4. RoPE + split Q/K; transpose + split V
    rope_split_kernel<<<SEQ, 256>>>();
    v_transpose_split_kernel<<<dim3(SEQ / 32, HDIM / 32, HEADS), dim3(32, 8)>>>();

    // 5. causal flash attention
    attn_mma_kernel<<<dim3(HEADS, SEQ / 64), 128, AT_SMEM>>>(attn);

    // 6. prep for O projection (reuse ah/al/bq/R)
    split_pad_kernel<<<(SEQ * HID) / (256 * 4), 256>>>(attn, ah, al);
    rowsum_ext_kernel<<<SEQ, 256>>>(attn, ah, al);
    qT_kernel<<<dim3(HID / 64, HID / 64), 256>>>(o_qw, bq, HID);
    prep_scales_kernel<<<HID / 32, 256>>>(o_s, o_z, R, bq, HID);

    // 7. output projection
    gemm_q_kernel<<<dim3(SEQ / 128, HID / 256), 256, gemm_smem>>>(
        ah, al, bq, R, out, SEQ, HID);
}

// round 14
// speedup vs baseline: 1.0730x; 1.0123x over previous
#include <cuda_runtime.h>
#include <cuda_bf16.h>
#include <cuda_fp16.h>
#include <math.h>
#include <stdint.h>

#define SEQ   2048
#define HID   4096
#define HEADS 32
#define HDIM  128
#define QKVN  12288
#define KPAD  4160          // 4096 + 64 ext cols (zero-correction)
#define NCH   130           // KPAD / 32

// ---------------- scratch (device globals; no runtime allocation) ----------------
__device__ float g_proj[(size_t)SEQ * QKVN];
__device__ float g_attn[(size_t)SEQ * HID];
__device__ float g_cos[SEQ * 64];
__device__ float g_sin[SEQ * 64];
__device__ float g_R[(size_t)32 * QKVN];                      // telescoping ratios
__device__ __half g_ah[(size_t)SEQ * KPAD];                   // activation hi (fp16)
__device__ __half g_al[(size_t)SEQ * KPAD];                   // activation lo
__device__ __half g_bq[(size_t)QKVN * KPAD];                  // exact q^T + ext cols
__device__ __nv_bfloat16 g_qh[(size_t)HEADS * SEQ * HDIM];
__device__ __nv_bfloat16 g_ql[(size_t)HEADS * SEQ * HDIM];
__device__ __nv_bfloat16 g_kh[(size_t)HEADS * SEQ * HDIM];
__device__ __nv_bfloat16 g_kl[(size_t)HEADS * SEQ * HDIM];
__device__ __nv_bfloat16 g_vth[(size_t)HEADS * HDIM * SEQ];
__device__ __nv_bfloat16 g_vtl[(size_t)HEADS * HDIM * SEQ];

__device__ __forceinline__ float neg_inf() { return __int_as_float(0xff800000); }

__device__ __forceinline__ uint32_t smem_to_u32(const void* p) {
    uint32_t a;
    asm("{ .reg .u64 t; cvta.to.shared.u64 t, %1; cvt.u32.u64 %0, t; }" : "=r"(a) : "l"(p));
    return a;
}
__device__ __forceinline__ void cp_async16(uint32_t dst, const void* src) {
    asm volatile("cp.async.cg.shared.global [%0], [%1], 16;" :: "r"(dst), "l"(src));
}
#define CP_COMMIT() asm volatile("cp.async.commit_group;" ::: "memory")
#define CP_WAIT(n)  asm volatile("cp.async.wait_group %0;" :: "n"(n) : "memory")

#define LDSM_X4(r, a) \
    asm volatile("ldmatrix.sync.aligned.m8n8.x4.shared.b16 {%0,%1,%2,%3}, [%4];" \
        : "=r"((r)[0]), "=r"((r)[1]), "=r"((r)[2]), "=r"((r)[3]) : "r"(a))
#define LDSM_X2(r, a) \
    asm volatile("ldmatrix.sync.aligned.m8n8.x2.shared.b16 {%0,%1}, [%2];" \
        : "=r"((r)[0]), "=r"((r)[1]) : "r"(a))
#define MMA_BF16(d, a, b) \
    asm volatile("mma.sync.aligned.m16n8k16.row.col.f32.bf16.bf16.f32 " \
        "{%0,%1,%2,%3}, {%4,%5,%6,%7}, {%8,%9}, {%0,%1,%2,%3};" \
        : "+f"((d)[0]), "+f"((d)[1]), "+f"((d)[2]), "+f"((d)[3]) \
        : "r"((a)[0]), "r"((a)[1]), "r"((a)[2]), "r"((a)[3]), "r"((b)[0]), "r"((b)[1]))
#define MMA_F16(d, a, b) \
    asm volatile("mma.sync.aligned.m16n8k16.row.col.f32.f16.f16.f32 " \
        "{%0,%1,%2,%3}, {%4,%5,%6,%7}, {%8,%9}, {%0,%1,%2,%3};" \
        : "+f"((d)[0]), "+f"((d)[1]), "+f"((d)[2]), "+f"((d)[3]) \
        : "r"((a)[0]), "r"((a)[1]), "r"((a)[2]), "r"((a)[3]), "r"((b)[0]), "r"((b)[1]))

__device__ __forceinline__ uint32_t swz(int r, int kbyte) {
    uint32_t seg = ((uint32_t)(kbyte >> 4)) ^ (((uint32_t)r >> 1) & 3u);
    return (uint32_t)r * 64u + (seg << 4) + (uint32_t)(kbyte & 15);
}

// ---------------- RoPE tables ----------------
__global__ void rope_tables_kernel(const int* __restrict__ pos_ids) {
    int s = blockIdx.x;
    int d = threadIdx.x;
    double inv = pow(10000.0, -(double)(2 * d) / 128.0);
    double ang = (double)pos_ids[s] * inv;
    g_cos[s * 64 + d] = (float)cos(ang);
    g_sin[s * 64 + d] = (float)sin(ang);
}

// ---------------- fp32 -> fp16 hi/lo split into padded [M][KPAD] ----------------
__global__ __launch_bounds__(256)
void split_pad_kernel(const float* __restrict__ X, __half* __restrict__ H,
                      __half* __restrict__ L) {
    int i = (blockIdx.x * 256 + threadIdx.x) * 4;
    int r = i >> 12, c = i & 4095;
    float4 v = *(const float4*)(X + i);
    size_t o = (size_t)r * KPAD + c;
    __half h0 = __float2half_rn(v.x), h1 = __float2half_rn(v.y);
    __half h2 = __float2half_rn(v.z), h3 = __float2half_rn(v.w);
    H[o + 0] = h0; H[o + 1] = h1; H[o + 2] = h2; H[o + 3] = h3;
    L[o + 0] = __float2half_rn(v.x - __half2float(h0));
    L[o + 1] = __float2half_rn(v.y - __half2float(h1));
    L[o + 2] = __float2half_rn(v.z - __half2float(h2));
    L[o + 3] = __float2half_rn(v.w - __half2float(h3));
}

// ---------------- per-row per-group sums -> ext cols of A ----------------
__global__ __launch_bounds__(256)
void rowsum_ext_kernel(const float* __restrict__ X, __half* __restrict__ H,
                       __half* __restrict__ L) {
    __shared__ float gs[32];
    int m = blockIdx.x;
    const float* row = X + (size_t)m * 4096;
    int g = threadIdx.x >> 3, l8 = threadIdx.x & 7;
    float s = 0.f;
    #pragma unroll
    for (int j = 0; j < 16; j++) s += row[g * 128 + l8 * 16 + j];
    s += __shfl_xor_sync(0xffffffffu, s, 1);
    s += __shfl_xor_sync(0xffffffffu, s, 2);
    s += __shfl_xor_sync(0xffffffffu, s, 4);
    if (l8 == 0) gs[g] = s;
    __syncthreads();
    if (threadIdx.x < 32) {
        float v = gs[threadIdx.x];
        __half h = __float2half_rn(v);
        __half lo = __float2half_rn(v - __half2float(h));
        size_t o = (size_t)m * KPAD + 4096 + threadIdx.x;
        H[o] = h; H[o + 32] = h;
        L[o] = lo; L[o + 32] = lo;
    }
}

// ---------------- q transpose: coalesced 64x64 tile (validated R13) ----------------
__global__ __launch_bounds__(256)
void qT_kernel(const int* __restrict__ Qw, __half* __restrict__ B, int N) {
    __shared__ int w[64][65];
    int n0 = blockIdx.x * 64, k0 = blockIdx.y * 64;
    int tid = threadIdx.x;
    int tx = tid & 15, ty = tid >> 4;
    #pragma unroll
    for (int p = 0; p < 4; p++) {
        int r = p * 16 + ty;
        int4 v = *(const int4*)(Qw + (size_t)(k0 + r) * N + n0 + tx * 4);
        w[r][tx * 4 + 0] = v.x; w[r][tx * 4 + 1] = v.y;
        w[r][tx * 4 + 2] = v.z; w[r][tx * 4 + 3] = v.w;
    }
    __syncthreads();
    int kx = tid & 7, ny = tid >> 3;
    #pragma unroll
    for (int p = 0; p < 2; p++) {
        int n = p * 32 + ny;
        __half h[8];
        #pragma unroll
        for (int j = 0; j < 8; j++) h[j] = __float2half_rn((float)w[kx * 8 + j][n]);
        *(uint4*)(B + (size_t)(n0 + n) * KPAD + k0 + kx * 8) = *(uint4*)h;
    }
}

// ---------------- scale prep: parallel (validated R12) ----------------
__global__ __launch_bounds__(256)
void prep_scales_kernel(const float* __restrict__ S, const float* __restrict__ Z,
                        float* __restrict__ R, __half* __restrict__ B, int N) {
    __shared__ float sp[32][33];
    int nl = threadIdx.x & 31, tg = threadIdx.x >> 5;
    int n = blockIdx.x * 32 + nl;
    #pragma unroll
    for (int j = 0; j < 4; j++) {
        int g = tg * 4 + j;
        float s = S[(size_t)g * N + n];
        float z = Z[(size_t)g * N + n];
        sp[g][nl] = fmaxf(s, 1e-30f);
        float t = -s * z;
        __half th = __float2half_rn(t);
        B[(size_t)n * KPAD + 4096 + g] = th;
        B[(size_t)n * KPAD + 4128 + g] = __float2half_rn(t - __half2float(th));
    }
    __syncthreads();
    #pragma unroll
    for (int j = 0; j < 4; j++) {
        int g = tg * 4 + j;
        R[(size_t)g * N + n] = (g < 31) ? sp[g][nl] / sp[g + 1][nl] : sp[31][nl];
    }
}

// ---------------- exact-q fp16 GEMM (R13 + paired B x4 LDSM) ----------------
#define GST_AH 0
#define GST_AL 8192
#define GST_B  16384
#define GSTAGE 32768

__global__ __launch_bounds__(256, 1)
void gemm_q_kernel(const __half* __restrict__ Ah, const __half* __restrict__ Al,
                   const __half* __restrict__ B, const float* __restrict__ R,
                   float* __restrict__ C, int M, int N) {
    extern __shared__ char smraw[];
    const uint32_t sb = smem_to_u32(smraw);
    const int tid = threadIdx.x, lane = tid & 31, wid = tid >> 5;
    const int m0 = blockIdx.x << 7, n0 = blockIdx.y << 8;
    const int wm = (wid & 1) << 6;
    const int wn = (wid >> 1) << 6;

    float acc[4][8][4];
    #pragma unroll
    for (int mi = 0; mi < 4; mi++)
        #pragma unroll
        for (int ni = 0; ni < 8; ni++)
            #pragma unroll
            for (int e = 0; e < 4; e++) acc[mi][ni][e] = 0.f;

    auto load_stage = [&](int buf, int c) {
        uint32_t stage = sb + (uint32_t)buf * GSTAGE;
        int k0 = c << 5;
        #pragma unroll
        for (int u = 0; u < 4; u++) {
            int idx = tid + u * 256;
            int hl = idx >> 9;
            int r = (idx & 511) >> 2, seg = idx & 3;
            const __half* src = hl ? Al : Ah;
            cp_async16(stage + (hl ? GST_AL : GST_AH) + swz(r, seg << 4),
                       src + (size_t)(m0 + r) * KPAD + k0 + seg * 8);
        }
        #pragma unroll
        for (int u = 0; u < 4; u++) {
            int idx = tid + u * 256;
            int r = idx >> 2, seg = idx & 3;
            cp_async16(stage + GST_B + swz(r, seg << 4),
                       B + (size_t)(n0 + r) * KPAD + k0 + seg * 8);
        }
        CP_COMMIT();
    };

    load_stage(0, 0);
    load_stage(1, 1);

    float rv[16];
    int buf = 0;
    for (int i = 0; i < NCH; i++) {
        if (i + 2 < NCH) {
            int nb = buf + 2; if (nb >= 3) nb -= 3;
            load_stage(nb, i + 2);
            CP_WAIT(2);
        } else if (i + 1 < NCH) {
            CP_WAIT(1);
        } else {
            CP_WAIT(0);
        }
        __syncthreads();

        if ((i & 3) == 0 && i < 128) {
            int g = i >> 2;
            #pragma unroll
            for (int j = 0; j < 16; j++)
                rv[j] = __ldg(&R[(size_t)g * N + n0 + wn + (j >> 1) * 8
                                 + (lane & 3) * 2 + (j & 1)]);
        }

        uint32_t stage = sb + (uint32_t)buf * GSTAGE;
        #pragma unroll
        for (int ks = 0; ks < 2; ks++) {
            uint32_t a_h[4][4], a_l[4][4];
            int akb = ks * 32 + ((lane >> 4) & 1) * 16;
            #pragma unroll
            for (int mi = 0; mi < 4; mi++) {
                int row = wm + mi * 16 + (lane & 15);
                uint32_t so = swz(row, akb);
                LDSM_X4(a_h[mi], stage + GST_AH + so);
                LDSM_X4(a_l[mi], stage + GST_AL + so);
            }
            // B: one x4 covers two adjacent n-blocks (lanes 16-31 -> block ni+1)
            int bkb = ks * 32 + ((lane >> 3) & 1) * 16;
            #pragma unroll
            for (int np = 0; np < 4; np++) {
                uint32_t b4[4];
                int row = wn + (np * 2 + ((lane >> 4) & 1)) * 8 + (lane & 7);
                LDSM_X4(b4, stage + GST_B + swz(row, bkb));
                #pragma unroll
                for (int mi = 0; mi < 4; mi++) {
                    MMA_F16(acc[mi][np * 2],     a_h[mi], b4);
                    MMA_F16(acc[mi][np * 2],     a_l[mi], b4);
                    MMA_F16(acc[mi][np * 2 + 1], a_h[mi], b4 + 2);
                    MMA_F16(acc[mi][np * 2 + 1], a_l[mi], b4 + 2);
                }
            }
        }

        if ((i & 3) == 3 && i < 128) {
            #pragma unroll
            for (int mi = 0; mi < 4; mi++)
                #pragma unroll
                for (int ni = 0; ni < 8; ni++) {
                    acc[mi][ni][0] *= rv[ni * 2];
                    acc[mi][ni][1] *= rv[ni * 2 + 1];
                    acc[mi][ni][2] *= rv[ni * 2];
                    acc[mi][ni][3] *= rv[ni * 2 + 1];
                }
        }
        __syncthreads();
        if (++buf == 3) buf = 0;
    }

    const int er = m0 + wm + (lane >> 2);
    const int ec = n0 + wn + (lane & 3) * 2;
    #pragma unroll
    for (int mi = 0; mi < 4; mi++) {
        #pragma unroll
        for (int ni = 0; ni < 8; ni++) {
            float* p = C + (size_t)(er + mi * 16) * N + ec + ni * 8;
            *(float2*)p                   = make_float2(acc[mi][ni][0], acc[mi][ni][1]);
            *(float2*)(p + 8 * (size_t)N) = make_float2(acc[mi][ni][2], acc[mi][ni][3]);
        }
    }
}

// ---------------- RoPE + split Q/K -> bf16 hi/lo [h][s][d] ----------------
__global__ __launch_bounds__(256)
void rope_split_kernel() {
    int s = blockIdx.x;
    const float* row = g_proj + (size_t)s * QKVN;
    for (int it = threadIdx.x; it < 4096; it += 256) {
        int qk = it >> 11;
        int hh = (it >> 6) & 31;
        int d  = it & 63;
        float c = g_cos[s * 64 + d], sn = g_sin[s * 64 + d];
        const float* p = row + qk * HID + hh * 128;
        float x1 = p[d], x2 = p[d + 64];
        float y1 = x1 * c - x2 * sn;
        float y2 = x2 * c + x1 * sn;
        if (qk == 0) { y1 *= 0.08838834764831845f; y2 *= 0.08838834764831845f; }
        __nv_bfloat16* H = qk ? g_kh : g_qh;
        __nv_bfloat16* L = qk ? g_kl : g_ql;
        size_t o = ((size_t)hh * SEQ + s) * 128 + d;
        __nv_bfloat16 h1 = __float2bfloat16(y1), h2 = __float2bfloat16(y2);
        H[o] = h1; H[o + 64] = h2;
        L[o]      = __float2bfloat16(y1 - __bfloat162float(h1));
        L[o + 64] = __float2bfloat16(y2 - __bfloat162float(h2));
    }
}

// ---------------- V transpose + split ----------------
__global__ void v_transpose_split_kernel() {
    __shared__ float t[32][33];
    int s0 = blockIdx.x * 32, d0 = blockIdx.y * 32, h = blockIdx.z;
    int tx = threadIdx.x, ty = threadIdx.y;
    #pragma unroll
    for (int rr = 0; rr < 32; rr += 8)
        t[rr + ty][tx] = g_proj[(size_t)(s0 + rr + ty) * QKVN + 2 * HID + h * 128 + d0 + tx];
    __syncthreads();
    #pragma unroll
    for (int rr = 0; rr < 32; rr += 8) {
        int d = d0 + rr + ty;
        float v = t[tx][rr + ty];
        __nv_bfloat16 hi = __float2bfloat16(v);
        size_t o = ((size_t)h * 128 + d) * SEQ + s0 + tx;
        g_vth[o] = hi;
        g_vtl[o] = __float2bfloat16(v - __bfloat162float(hi));
    }
}

// ---------------- bf16x3 mma.sync flash attention (R13 + paired hi/lo x4 LDSM) -------
#define QPITCH 272
#define VPITCH 144
#define AT_QH  0
#define AT_QL  17408
#define AT_K0  34816
#define KV_KH  0
#define KV_KL  17408
#define KV_VH  34816
#define KV_VL  53248
#define AT_STAGE 71680
#define AT_SMEM  (AT_K0 + 2 * AT_STAGE)

__global__ __launch_bounds__(128, 1)
void attn_mma_kernel(float* __restrict__ out) {
    extern __shared__ char smraw[];
    const uint32_t sb = smem_to_u32(smraw);
    const int h  = blockIdx.x;
    const int qt = (int)gridDim.y - 1 - (int)blockIdx.y;
    const int tid = threadIdx.x, lane = tid & 31, warp = tid >> 5;
    const int wm16 = warp << 4;

    const __nv_bfloat16* qhp = g_qh + ((size_t)h * SEQ + qt * 64) * 128;
    const __nv_bfloat16* qlp = g_ql + ((size_t)h * SEQ + qt * 64) * 128;
    const __nv_bfloat16* kh0 = g_kh + (size_t)h * SEQ * 128;
    const __nv_bfloat16* kl0 = g_kl + (size_t)h * SEQ * 128;
    const __nv_bfloat16* vh0 = g_vth + (size_t)h * 128 * SEQ;
    const __nv_bfloat16* vl0 = g_vtl + (size_t)h * 128 * SEQ;

    auto load_kv = [&](int kt_, int buf_) {
        uint32_t base = sb + AT_K0 + (uint32_t)buf_ * AT_STAGE;
        const __nv_bfloat16* kh = kh0 + (size_t)kt_ * 64 * 128;
        const __nv_bfloat16* kl = kl0 + (size_t)kt_ * 64 * 128;
        #pragma unroll
        for (int u = 0; u < 16; u++) {
            int i = tid + u * 128;
            int m = i >> 10, c = i & 1023, r = c >> 4, seg = c & 15;
            cp_async16(base + m * 17408 + r * QPITCH + seg * 16,
                       (m ? kl : kh) + r * 128 + seg * 8);
        }
        const __nv_bfloat16* vh = vh0 + kt_ * 64;
        const __nv_bfloat16* vl = vl0 + kt_ * 64;
        #pragma unroll
        for (int u = 0; u < 16; u++) {
            int i = tid + u * 128;
            int m = i >> 10, c = i & 1023, r = c >> 3, seg = c & 7;
            cp_async16(base + KV_VH + m * 18432 + r * VPITCH + seg * 16,
                       (m ? vl : vh) + (size_t)r * SEQ + seg * 8);
        }
    };

    #pragma unroll
    for (int u = 0; u < 16; u++) {
        int i = tid + u * 128;
        int m = i >> 10, c = i & 1023, r = c >> 4, seg = c & 15;
        const __nv_bfloat16* src = m ? qlp : qhp;
        cp_async16(sb + (m ? AT_QL : AT_QH) + r * QPITCH + seg * 16,
                   src + r * 128 + seg * 8);
    }
    load_kv(0, 0);
    CP_COMMIT();

    float o[16][4];
    #pragma unroll
    for (int n = 0; n < 16; n++)
        #pragma unroll
        for (int e = 0; e < 4; e++) o[n][e] = 0.f;
    float m0 = neg_inf(), m1 = neg_inf(), l0 = 0.f, l1 = 0.f;

    for (int kt = 0; kt <= qt; kt++) {
        int buf = kt & 1;
        if (kt < qt) {
            load_kv(kt + 1, buf ^ 1);
            CP_COMMIT();
            CP_WAIT(1);
        } else {
            CP_WAIT(0);
        }
        __syncthreads();

        uint32_t kvb = sb + AT_K0 + (uint32_t)buf * AT_STAGE;

        float s4[8][4];
        #pragma unroll
        for (int j = 0; j < 8; j++)
            #pragma unroll
            for (int e = 0; e < 4; e++) s4[j][e] = 0.f;
        #pragma unroll
        for (int ks = 0; ks < 8; ks++) {
            uint32_t ah[4], al[4];
            uint32_t qa = (uint32_t)(wm16 + (lane & 15)) * QPITCH
                        + ks * 32 + ((lane >> 4) & 1) * 16;
            LDSM_X4(ah, sb + AT_QH + qa);
            LDSM_X4(al, sb + AT_QL + qa);
            #pragma unroll
            for (int j = 0; j < 8; j++) {
                // one x4: lanes 0-15 -> KH fragment, lanes 16-31 -> KL fragment
                uint32_t b4[4];
                uint32_t ka = (uint32_t)(j * 8 + (lane & 7)) * QPITCH
                            + ks * 32 + ((lane >> 3) & 1) * 16
                            + ((lane >> 4) & 1) * 17408u;
                LDSM_X4(b4, kvb + KV_KH + ka);
                MMA_BF16(s4[j], ah, b4);        // Qh·Kh
                MMA_BF16(s4[j], al, b4);        // Ql·Kh
                MMA_BF16(s4[j], ah, b4 + 2);    // Qh·Kl
            }
        }

        if (kt == qt) {
            int colb = 2 * (lane & 3);
            int rowb = wm16 + (lane >> 2);
            #pragma unroll
            for (int j = 0; j < 8; j++) {
                int c0 = j * 8 + colb;
                if (c0     > rowb)     s4[j][0] = neg_inf();
                if (c0 + 1 > rowb)     s4[j][1] = neg_inf();
                if (c0     > rowb + 8) s4[j][2] = neg_inf();
                if (c0 + 1 > rowb + 8) s4[j][3] = neg_inf();
            }
        }

        float tm0 = neg_inf(), tm1 = neg_inf();
        #pragma unroll
        for (int j = 0; j < 8; j++) {
            tm0 = fmaxf(tm0, fmaxf(s4[j][0], s4[j][1]));
            tm1 = fmaxf(tm1, fmaxf(s4[j][2], s4[j][3]));
        }
        tm0 = fmaxf(tm0, __shfl_xor_sync(0xffffffffu, tm0, 1));
        tm0 = fmaxf(tm0, __shfl_xor_sync(0xffffffffu, tm0, 2));
        tm1 = fmaxf(tm1, __shfl_xor_sync(0xffffffffu, tm1, 1));
        tm1 = fmaxf(tm1, __shfl_xor_sync(0xffffffffu, tm1, 2));
        float mn0 = fmaxf(m0, tm0), mn1 = fmaxf(m1, tm1);
        float a0 = __expf(m0 - mn0), a1 = __expf(m1 - mn1);
        m0 = mn0; m1 = mn1;

        float rs0 = 0.f, rs1 = 0.f;
        uint32_t pah[4][4], pal[4][4];
        #pragma unroll
        for (int j = 0; j < 8; j++) {
            float p0 = __expf(s4[j][0] - mn0), p1 = __expf(s4[j][1] - mn0);
            float p2 = __expf(s4[j][2] - mn1), p3 = __expf(s4[j][3] - mn1);
            rs0 += p0 + p1; rs1 += p2 + p3;
            __nv_bfloat16 b0 = __float2bfloat16(p0), b1 = __float2bfloat16(p1);
            __nv_bfloat16 b2 = __float2bfloat16(p2), b3 = __float2bfloat16(p3);
            uint32_t h01 = ((uint32_t)__bfloat16_as_ushort(b1) << 16) | __bfloat16_as_ushort(b0);
            uint32_t h23 = ((uint32_t)__bfloat16_as_ushort(b3) << 16) | __bfloat16_as_ushort(b2);
            __nv_bfloat16 c0 = __float2bfloat16(p0 - __bfloat162float(b0));
            __nv_bfloat16 c1 = __float2bfloat16(p1 - __bfloat162float(b1));
            __nv_bfloat16 c2 = __float2bfloat16(p2 - __bfloat162float(b2));
            __nv_bfloat16 c3 = __float2bfloat16(p3 - __bfloat162float(b3));
            uint32_t l01 = ((uint32_t)__bfloat16_as_ushort(c1) << 16) | __bfloat16_as_ushort(c0);
            uint32_t l23 = ((uint32_t)__bfloat16_as_ushort(c3) << 16) | __bfloat16_as_ushort(c2);
            int k2 = j >> 1, odd = (j & 1) << 1;
            pah[k2][odd] = h01; pah[k2][odd + 1] = h23;
            pal[k2][odd] = l01; pal[k2][odd + 1] = l23;
        }
        rs0 += __shfl_xor_sync(0xffffffffu, rs0, 1);
        rs0 += __shfl_xor_sync(0xffffffffu, rs0, 2);
        rs1 += __shfl_xor_sync(0xffffffffu, rs1, 1);
        rs1 += __shfl_xor_sync(0xffffffffu, rs1, 2);
        l0 = l0 * a0 + rs0;
        l1 = l1 * a1 + rs1;
        #pragma unroll
        for (int n = 0; n < 16; n++) {
            o[n][0] *= a0; o[n][1] *= a0; o[n][2] *= a1; o[n][3] *= a1;
        }

        #pragma unroll
        for (int ks2 = 0; ks2 < 4; ks2++) {
            #pragma unroll
            for (int n = 0; n < 16; n++) {
                // one x4: lanes 0-15 -> VH fragment, lanes 16-31 -> VL fragment
                uint32_t v4[4];
                uint32_t va = (uint32_t)(n * 8 + (lane & 7)) * VPITCH
                            + ks2 * 32 + ((lane >> 3) & 1) * 16
                            + ((lane >> 4) & 1) * 18432u;
                LDSM_X4(v4, kvb + KV_VH + va);
                MMA_BF16(o[n], pah[ks2], v4);        // Ph·Vh
                MMA_BF16(o[n], pal[ks2], v4);        // Pl·Vh
                MMA_BF16(o[n], pah[ks2], v4 + 2);    // Ph·Vl
            }
        }
        __syncthreads();
    }

    float inv0 = 1.f / l0, inv1 = 1.f / l1;
    int rg = qt * 64 + wm16 + (lane >> 2);
    int cb = h * 128 + 2 * (lane & 3);
    #pragma unroll
    for (int n = 0; n < 16; n++) {
        float* p0 = out + (size_t)rg * HID + cb + n * 8;
        *(float2*)p0 = make_float2(o[n][0] * inv0, o[n][1] * inv0);
        float* p1 = out + (size_t)(rg + 8) * HID + cb + n * 8;
        *(float2*)p1 = make_float2(o[n][2] * inv1, o[n][3] * inv1);
    }
}

extern "C" void kernel_launch(void* const* d_in, const int* in_sizes, int n_in,
                              void* d_out, int out_size) {
    const float* hidden = (const float*)d_in[0];
    const int*   pos    = (const int*)d_in[1];
    const int*   qkv_qw = (const int*)d_in[2];
    const float* qkv_s  = (const float*)d_in[3];
    const float* qkv_z  = (const float*)d_in[4];
    const int*   o_qw   = (const int*)d_in[5];
    const float* o_s    = (const float*)d_in[6];
    const float* o_z    = (const float*)d_in[7];
    float* out = (float*)d_out;

    void* p;
    cudaGetSymbolAddress(&p, g_proj); float* proj = (float*)p;
    cudaGetSymbolAddress(&p, g_attn); float* attn = (float*)p;
    cudaGetSymbolAddress(&p, g_R);    float* R    = (float*)p;
    cudaGetSymbolAddress(&p, g_ah);   __half* ah  = (__half*)p;
    cudaGetSymbolAddress(&p, g_al);   __half* al  = (__half*)p;
    cudaGetSymbolAddress(&p, g_bq);   __half* bq  = (__half*)p;

    int gemm_smem = 3 * GSTAGE;                       // 98304
    cudaFuncSetAttribute(gemm_q_kernel,
                         cudaFuncAttributeMaxDynamicSharedMemorySize, gemm_smem);
    cudaFuncSetAttribute(attn_mma_kernel,
                         cudaFuncAttributeMaxDynamicSharedMemorySize, AT_SMEM);

    // 1. RoPE tables
    rope_tables_kernel<<<SEQ, 64>>>(pos);

    // 2. prep: activations (hi/lo + group rowsums), exact-q weights, scales
    split_pad_kernel<<<(SEQ * HID) / (256 * 4), 256>>>(hidden, ah, al);
    rowsum_ext_kernel<<<SEQ, 256>>>(hidden, ah, al);
    qT_kernel<<<dim3(QKVN / 64, HID / 64), 256>>>(qkv_qw, bq, QKVN);
    prep_scales_kernel<<<QKVN / 32, 256>>>(qkv_s, qkv_z, R, bq, QKVN);

    // 3. QKV projection (exact-q GEMM)
    gemm_q_kernel<<<dim3(SEQ / 128, QKVN / 256), 256, gemm_smem>>>(
        ah, al, bq, R, proj, SEQ, QKVN);

    // 4. RoPE + split Q/K; transpose + split V
    rope_split_kernel<<<SEQ, 256>>>();
    v_transpose_split_kernel<<<dim3(SEQ / 32, HDIM / 32, HEADS), dim3(32, 8)>>>();

    // 5. causal flash attention
    attn_mma_kernel<<<dim3(HEADS, SEQ / 64), 128, AT_SMEM>>>(attn);

    // 6. prep for O projection (reuse ah/al/bq/R)
    split_pad_kernel<<<(SEQ * HID) / (256 * 4), 256>>>(attn, ah, al);
    rowsum_ext_kernel<<<SEQ, 256>>>(attn, ah, al);
    qT_kernel<<<dim3(HID / 64, HID / 64), 256>>>(o_qw, bq, HID);
    prep_scales_kernel<<<HID / 32, 256>>>(o_s, o_z, R, bq, HID);

    // 7. output projection
    gemm_q_kernel<<<dim3(SEQ / 128, HID / 256), 256, gemm_smem>>>(
        ah, al, bq, R, out, SEQ, HID);
}

// round 15
// speedup vs baseline: 1.1197x; 1.0435x over previous
#include <cuda_runtime.h>
#include <cuda_bf16.h>
#include <cuda_fp16.h>
#include <math.h>
#include <stdint.h>

#define SEQ   2048
#define HID   4096
#define HEADS 32
#define HDIM  128
#define QKVN  12288
#define KPAD  4160          // 4096 + 64 ext cols (zero-correction)
#define NCH64 65            // KPAD / 64

// ---------------- scratch (device globals; no runtime allocation) ----------------
__device__ float g_proj[(size_t)SEQ * QKVN];
__device__ float g_attn[(size_t)SEQ * HID];
__device__ float g_cos[SEQ * 64];
__device__ float g_sin[SEQ * 64];
__device__ float g_R[(size_t)32 * QKVN];                      // telescoping ratios
__device__ __half g_ah[(size_t)SEQ * KPAD];                   // activation hi (fp16)
__device__ __half g_al[(size_t)SEQ * KPAD];                   // activation lo
__device__ __half g_bq[(size_t)QKVN * KPAD];                  // exact q^T + ext cols
__device__ __nv_bfloat16 g_qh[(size_t)HEADS * SEQ * HDIM];
__device__ __nv_bfloat16 g_ql[(size_t)HEADS * SEQ * HDIM];
__device__ __nv_bfloat16 g_kh[(size_t)HEADS * SEQ * HDIM];
__device__ __nv_bfloat16 g_kl[(size_t)HEADS * SEQ * HDIM];
__device__ __nv_bfloat16 g_vth[(size_t)HEADS * HDIM * SEQ];
__device__ __nv_bfloat16 g_vtl[(size_t)HEADS * HDIM * SEQ];

__device__ __forceinline__ float neg_inf() { return __int_as_float(0xff800000); }

__device__ __forceinline__ uint32_t smem_to_u32(const void* p) {
    uint32_t a;
    asm("{ .reg .u64 t; cvta.to.shared.u64 t, %1; cvt.u32.u64 %0, t; }" : "=r"(a) : "l"(p));
    return a;
}
__device__ __forceinline__ void cp_async16(uint32_t dst, const void* src) {
    asm volatile("cp.async.cg.shared.global [%0], [%1], 16;" :: "r"(dst), "l"(src));
}
#define CP_COMMIT() asm volatile("cp.async.commit_group;" ::: "memory")
#define CP_WAIT(n)  asm volatile("cp.async.wait_group %0;" :: "n"(n) : "memory")

#define LDSM_X4(r, a) \
    asm volatile("ldmatrix.sync.aligned.m8n8.x4.shared.b16 {%0,%1,%2,%3}, [%4];" \
        : "=r"((r)[0]), "=r"((r)[1]), "=r"((r)[2]), "=r"((r)[3]) : "r"(a))
#define LDSM_X2(r, a) \
    asm volatile("ldmatrix.sync.aligned.m8n8.x2.shared.b16 {%0,%1}, [%2];" \
        : "=r"((r)[0]), "=r"((r)[1]) : "r"(a))
#define MMA_BF16(d, a, b) \
    asm volatile("mma.sync.aligned.m16n8k16.row.col.f32.bf16.bf16.f32 " \
        "{%0,%1,%2,%3}, {%4,%5,%6,%7}, {%8,%9}, {%0,%1,%2,%3};" \
        : "+f"((d)[0]), "+f"((d)[1]), "+f"((d)[2]), "+f"((d)[3]) \
        : "r"((a)[0]), "r"((a)[1]), "r"((a)[2]), "r"((a)[3]), "r"((b)[0]), "r"((b)[1]))
#define MMA_F16(d, a, b) \
    asm volatile("mma.sync.aligned.m16n8k16.row.col.f32.f16.f16.f32 " \
        "{%0,%1,%2,%3}, {%4,%5,%6,%7}, {%8,%9}, {%0,%1,%2,%3};" \
        : "+f"((d)[0]), "+f"((d)[1]), "+f"((d)[2]), "+f"((d)[3]) \
        : "r"((a)[0]), "r"((a)[1]), "r"((a)[2]), "r"((a)[3]), "r"((b)[0]), "r"((b)[1]))

// 64B-row swizzle (attention tiles, validated)
__device__ __forceinline__ uint32_t swz(int r, int kbyte) {
    uint32_t seg = ((uint32_t)(kbyte >> 4)) ^ (((uint32_t)r >> 1) & 3u);
    return (uint32_t)r * 64u + (seg << 4) + (uint32_t)(kbyte & 15);
}
// 128B-row swizzle (GEMM BK=64 tiles): seg ^= r&7 -> conflict-free stores + ldmatrix
__device__ __forceinline__ uint32_t swz128(int r, int kbyte) {
    return (uint32_t)r * 128u + ((uint32_t)kbyte ^ (((uint32_t)r & 7u) << 4));
}

// ---------------- RoPE tables ----------------
__global__ void rope_tables_kernel(const int* __restrict__ pos_ids) {
    int s = blockIdx.x;
    int d = threadIdx.x;
    double inv = pow(10000.0, -(double)(2 * d) / 128.0);
    double ang = (double)pos_ids[s] * inv;
    g_cos[s * 64 + d] = (float)cos(ang);
    g_sin[s * 64 + d] = (float)sin(ang);
}

// ---------------- fp32 -> fp16 hi/lo split into padded [M][KPAD] ----------------
__global__ __launch_bounds__(256)
void split_pad_kernel(const float* __restrict__ X, __half* __restrict__ H,
                      __half* __restrict__ L) {
    int i = (blockIdx.x * 256 + threadIdx.x) * 4;
    int r = i >> 12, c = i & 4095;
    float4 v = *(const float4*)(X + i);
    size_t o = (size_t)r * KPAD + c;
    __half h0 = __float2half_rn(v.x), h1 = __float2half_rn(v.y);
    __half h2 = __float2half_rn(v.z), h3 = __float2half_rn(v.w);
    H[o + 0] = h0; H[o + 1] = h1; H[o + 2] = h2; H[o + 3] = h3;
    L[o + 0] = __float2half_rn(v.x - __half2float(h0));
    L[o + 1] = __float2half_rn(v.y - __half2float(h1));
    L[o + 2] = __float2half_rn(v.z - __half2float(h2));
    L[o + 3] = __float2half_rn(v.w - __half2float(h3));
}

// ---------------- per-row per-group sums -> ext cols of A ----------------
__global__ __launch_bounds__(256)
void rowsum_ext_kernel(const float* __restrict__ X, __half* __restrict__ H,
                       __half* __restrict__ L) {
    __shared__ float gs[32];
    int m = blockIdx.x;
    const float* row = X + (size_t)m * 4096;
    int g = threadIdx.x >> 3, l8 = threadIdx.x & 7;
    float s = 0.f;
    #pragma unroll
    for (int j = 0; j < 16; j++) s += row[g * 128 + l8 * 16 + j];
    s += __shfl_xor_sync(0xffffffffu, s, 1);
    s += __shfl_xor_sync(0xffffffffu, s, 2);
    s += __shfl_xor_sync(0xffffffffu, s, 4);
    if (l8 == 0) gs[g] = s;
    __syncthreads();
    if (threadIdx.x < 32) {
        float v = gs[threadIdx.x];
        __half h = __float2half_rn(v);
        __half lo = __float2half_rn(v - __half2float(h));
        size_t o = (size_t)m * KPAD + 4096 + threadIdx.x;
        H[o] = h; H[o + 32] = h;
        L[o] = lo; L[o + 32] = lo;
    }
}

// ---------------- q transpose: coalesced 64x64 tile (validated R13) ----------------
__global__ __launch_bounds__(256)
void qT_kernel(const int* __restrict__ Qw, __half* __restrict__ B, int N) {
    __shared__ int w[64][65];
    int n0 = blockIdx.x * 64, k0 = blockIdx.y * 64;
    int tid = threadIdx.x;
    int tx = tid & 15, ty = tid >> 4;
    #pragma unroll
    for (int p = 0; p < 4; p++) {
        int r = p * 16 + ty;
        int4 v = *(const int4*)(Qw + (size_t)(k0 + r) * N + n0 + tx * 4);
        w[r][tx * 4 + 0] = v.x; w[r][tx * 4 + 1] = v.y;
        w[r][tx * 4 + 2] = v.z; w[r][tx * 4 + 3] = v.w;
    }
    __syncthreads();
    int kx = tid & 7, ny = tid >> 3;
    #pragma unroll
    for (int p = 0; p < 2; p++) {
        int n = p * 32 + ny;
        __half h[8];
        #pragma unroll
        for (int j = 0; j < 8; j++) h[j] = __float2half_rn((float)w[kx * 8 + j][n]);
        *(uint4*)(B + (size_t)(n0 + n) * KPAD + k0 + kx * 8) = *(uint4*)h;
    }
}

// ---------------- scale prep: parallel (validated R12) ----------------
__global__ __launch_bounds__(256)
void prep_scales_kernel(const float* __restrict__ S, const float* __restrict__ Z,
                        float* __restrict__ R, __half* __restrict__ B, int N) {
    __shared__ float sp[32][33];
    int nl = threadIdx.x & 31, tg = threadIdx.x >> 5;
    int n = blockIdx.x * 32 + nl;
    #pragma unroll
    for (int j = 0; j < 4; j++) {
        int g = tg * 4 + j;
        float s = S[(size_t)g * N + n];
        float z = Z[(size_t)g * N + n];
        sp[g][nl] = fmaxf(s, 1e-30f);
        float t = -s * z;
        __half th = __float2half_rn(t);
        B[(size_t)n * KPAD + 4096 + g] = th;
        B[(size_t)n * KPAD + 4128 + g] = __float2half_rn(t - __half2float(th));
    }
    __syncthreads();
    #pragma unroll
    for (int j = 0; j < 4; j++) {
        int g = tg * 4 + j;
        R[(size_t)g * N + n] = (g < 31) ? sp[g][nl] / sp[g + 1][nl] : sp[31][nl];
    }
}

// ---------------- exact-q fp16 GEMM: BK=64, 2-stage (ONLY change vs R14) --------------
#define GST_AH 0
#define GST_AL 16384
#define GST_B  32768
#define GSTAGE 65536

__global__ __launch_bounds__(256, 1)
void gemm_q_kernel(const __half* __restrict__ Ah, const __half* __restrict__ Al,
                   const __half* __restrict__ B, const float* __restrict__ R,
                   float* __restrict__ C, int M, int N) {
    extern __shared__ char smraw[];
    const uint32_t sb = smem_to_u32(smraw);
    const int tid = threadIdx.x, lane = tid & 31, wid = tid >> 5;
    const int m0 = blockIdx.x << 7, n0 = blockIdx.y << 8;
    const int wm = (wid & 1) << 6;
    const int wn = (wid >> 1) << 6;

    float acc[4][8][4];
    #pragma unroll
    for (int mi = 0; mi < 4; mi++)
        #pragma unroll
        for (int ni = 0; ni < 8; ni++)
            #pragma unroll
            for (int e = 0; e < 4; e++) acc[mi][ni][e] = 0.f;

    auto load_stage = [&](int buf, int c) {
        uint32_t stage = sb + (uint32_t)buf * GSTAGE;
        int k0 = c << 6;
        #pragma unroll
        for (int u = 0; u < 8; u++) {            // A hi+lo: 2048 x 16B
            int idx = tid + u * 256;
            int hl = idx >> 10;
            int r = (idx & 1023) >> 3, seg = idx & 7;
            const __half* src = hl ? Al : Ah;
            cp_async16(stage + (hl ? GST_AL : GST_AH) + swz128(r, seg << 4),
                       src + (size_t)(m0 + r) * KPAD + k0 + seg * 8);
        }
        #pragma unroll
        for (int u = 0; u < 8; u++) {            // B: 2048 x 16B (256 rows x 128B)
            int idx = tid + u * 256;
            int r = idx >> 3, seg = idx & 7;
            cp_async16(stage + GST_B + swz128(r, seg << 4),
                       B + (size_t)(n0 + r) * KPAD + k0 + seg * 8);
        }
        CP_COMMIT();
    };

    load_stage(0, 0);

    float rv[16];
    int buf = 0;
    for (int i = 0; i < NCH64; i++) {
        if (i + 1 < NCH64) {
            load_stage(buf ^ 1, i + 1);
            CP_WAIT(1);
        } else {
            CP_WAIT(0);
        }
        __syncthreads();

        if ((i & 1) == 0 && i < 64) {
            int g = i >> 1;
            #pragma unroll
            for (int j = 0; j < 16; j++)
                rv[j] = __ldg(&R[(size_t)g * N + n0 + wn + (j >> 1) * 8
                                 + (lane & 3) * 2 + (j & 1)]);
        }

        uint32_t stage = sb + (uint32_t)buf * GSTAGE;
        #pragma unroll
        for (int ks = 0; ks < 4; ks++) {
            uint32_t a_h[4][4], a_l[4][4];
            int akb = ks * 32 + ((lane >> 4) & 1) * 16;
            #pragma unroll
            for (int mi = 0; mi < 4; mi++) {
                int row = wm + mi * 16 + (lane & 15);
                uint32_t so = swz128(row, akb);
                LDSM_X4(a_h[mi], stage + GST_AH + so);
                LDSM_X4(a_l[mi], stage + GST_AL + so);
            }
            int bkb = ks * 32 + ((lane >> 3) & 1) * 16;
            #pragma unroll
            for (int np = 0; np < 4; np++) {
                uint32_t b4[4];
                int row = wn + (np * 2 + ((lane >> 4) & 1)) * 8 + (lane & 7);
                LDSM_X4(b4, stage + GST_B + swz128(row, bkb));
                #pragma unroll
                for (int mi = 0; mi < 4; mi++) {
                    MMA_F16(acc[mi][np * 2],     a_h[mi], b4);
                    MMA_F16(acc[mi][np * 2],     a_l[mi], b4);
                    MMA_F16(acc[mi][np * 2 + 1], a_h[mi], b4 + 2);
                    MMA_F16(acc[mi][np * 2 + 1], a_l[mi], b4 + 2);
                }
            }
        }

        if ((i & 1) == 1 && i < 64) {
            #pragma unroll
            for (int mi = 0; mi < 4; mi++)
                #pragma unroll
                for (int ni = 0; ni < 8; ni++) {
                    acc[mi][ni][0] *= rv[ni * 2];
                    acc[mi][ni][1] *= rv[ni * 2 + 1];
                    acc[mi][ni][2] *= rv[ni * 2];
                    acc[mi][ni][3] *= rv[ni * 2 + 1];
                }
        }
        __syncthreads();
        buf ^= 1;
    }

    const int er = m0 + wm + (lane >> 2);
    const int ec = n0 + wn + (lane & 3) * 2;
    #pragma unroll
    for (int mi = 0; mi < 4; mi++) {
        #pragma unroll
        for (int ni = 0; ni < 8; ni++) {
            float* p = C + (size_t)(er + mi * 16) * N + ec + ni * 8;
            *(float2*)p                   = make_float2(acc[mi][ni][0], acc[mi][ni][1]);
            *(float2*)(p + 8 * (size_t)N) = make_float2(acc[mi][ni][2], acc[mi][ni][3]);
        }
    }
}

// ---------------- RoPE + split Q/K -> bf16 hi/lo [h][s][d] ----------------
__global__ __launch_bounds__(256)
void rope_split_kernel() {
    int s = blockIdx.x;
    const float* row = g_proj + (size_t)s * QKVN;
    for (int it = threadIdx.x; it < 4096; it += 256) {
        int qk = it >> 11;
        int hh = (it >> 6) & 31;
        int d  = it & 63;
        float c = g_cos[s * 64 + d], sn = g_sin[s * 64 + d];
        const float* p = row + qk * HID + hh * 128;
        float x1 = p[d], x2 = p[d + 64];
        float y1 = x1 * c - x2 * sn;
        float y2 = x2 * c + x1 * sn;
        if (qk == 0) { y1 *= 0.08838834764831845f; y2 *= 0.08838834764831845f; }
        __nv_bfloat16* H = qk ? g_kh : g_qh;
        __nv_bfloat16* L = qk ? g_kl : g_ql;
        size_t o = ((size_t)hh * SEQ + s) * 128 + d;
        __nv_bfloat16 h1 = __float2bfloat16(y1), h2 = __float2bfloat16(y2);
        H[o] = h1; H[o + 64] = h2;
        L[o]      = __float2bfloat16(y1 - __bfloat162float(h1));
        L[o + 64] = __float2bfloat16(y2 - __bfloat162float(h2));
    }
}

// ---------------- V transpose + split ----------------
__global__ void v_transpose_split_kernel() {
    __shared__ float t[32][33];
    int s0 = blockIdx.x * 32, d0 = blockIdx.y * 32, h = blockIdx.z;
    int tx = threadIdx.x, ty = threadIdx.y;
    #pragma unroll
    for (int rr = 0; rr < 32; rr += 8)
        t[rr + ty][tx] = g_proj[(size_t)(s0 + rr + ty) * QKVN + 2 * HID + h * 128 + d0 + tx];
    __syncthreads();
    #pragma unroll
    for (int rr = 0; rr < 32; rr += 8) {
        int d = d0 + rr + ty;
        float v = t[tx][rr + ty];
        __nv_bfloat16 hi = __float2bfloat16(v);
        size_t o = ((size_t)h * 128 + d) * SEQ + s0 + tx;
        g_vth[o] = hi;
        g_vtl[o] = __float2bfloat16(v - __bfloat162float(hi));
    }
}

// ---------------- bf16x3 mma.sync flash attention (R14 exact) ----------------
#define QPITCH 272
#define VPITCH 144
#define AT_QH  0
#define AT_QL  17408
#define AT_K0  34816
#define KV_KH  0
#define KV_KL  17408
#define KV_VH  34816
#define KV_VL  53248
#define AT_STAGE 71680
#define AT_SMEM  (AT_K0 + 2 * AT_STAGE)

__global__ __launch_bounds__(128, 1)
void attn_mma_kernel(float* __restrict__ out) {
    extern __shared__ char smraw[];
    const uint32_t sb = smem_to_u32(smraw);
    const int h  = blockIdx.x;
    const int qt = (int)gridDim.y - 1 - (int)blockIdx.y;
    const int tid = threadIdx.x, lane = tid & 31, warp = tid >> 5;
    const int wm16 = warp << 4;

    const __nv_bfloat16* qhp = g_qh + ((size_t)h * SEQ + qt * 64) * 128;
    const __nv_bfloat16* qlp = g_ql + ((size_t)h * SEQ + qt * 64) * 128;
    const __nv_bfloat16* kh0 = g_kh + (size_t)h * SEQ * 128;
    const __nv_bfloat16* kl0 = g_kl + (size_t)h * SEQ * 128;
    const __nv_bfloat16* vh0 = g_vth + (size_t)h * 128 * SEQ;
    const __nv_bfloat16* vl0 = g_vtl + (size_t)h * 128 * SEQ;

    auto load_kv = [&](int kt_, int buf_) {
        uint32_t base = sb + AT_K0 + (uint32_t)buf_ * AT_STAGE;
        const __nv_bfloat16* kh = kh0 + (size_t)kt_ * 64 * 128;
        const __nv_bfloat16* kl = kl0 + (size_t)kt_ * 64 * 128;
        #pragma unroll
        for (int u = 0; u < 16; u++) {
            int i = tid + u * 128;
            int m = i >> 10, c = i & 1023, r = c >> 4, seg = c & 15;
            cp_async16(base + m * 17408 + r * QPITCH + seg * 16,
                       (m ? kl : kh) + r * 128 + seg * 8);
        }
        const __nv_bfloat16* vh = vh0 + kt_ * 64;
        const __nv_bfloat16* vl = vl0 + kt_ * 64;
        #pragma unroll
        for (int u = 0; u < 16; u++) {
            int i = tid + u * 128;
            int m = i >> 10, c = i & 1023, r = c >> 3, seg = c & 7;
            cp_async16(base + KV_VH + m * 18432 + r * VPITCH + seg * 16,
                       (m ? vl : vh) + (size_t)r * SEQ + seg * 8);
        }
    };

    #pragma unroll
    for (int u = 0; u < 16; u++) {
        int i = tid + u * 128;
        int m = i >> 10, c = i & 1023, r = c >> 4, seg = c & 15;
        const __nv_bfloat16* src = m ? qlp : qhp;
        cp_async16(sb + (m ? AT_QL : AT_QH) + r * QPITCH + seg * 16,
                   src + r * 128 + seg * 8);
    }
    load_kv(0, 0);
    CP_COMMIT();

    float o[16][4];
    #pragma unroll
    for (int n = 0; n < 16; n++)
        #pragma unroll
        for (int e = 0; e < 4; e++) o[n][e] = 0.f;
    float m0 = neg_inf(), m1 = neg_inf(), l0 = 0.f, l1 = 0.f;

    for (int kt = 0; kt <= qt; kt++) {
        int buf = kt & 1;
        if (kt < qt) {
            load_kv(kt + 1, buf ^ 1);
            CP_COMMIT();
            CP_WAIT(1);
        } else {
            CP_WAIT(0);
        }
        __syncthreads();

        uint32_t kvb = sb + AT_K0 + (uint32_t)buf * AT_STAGE;

        float s4[8][4];
        #pragma unroll
        for (int j = 0; j < 8; j++)
            #pragma unroll
            for (int e = 0; e < 4; e++) s4[j][e] = 0.f;
        #pragma unroll
        for (int ks = 0; ks < 8; ks++) {
            uint32_t ah[4], al[4];
            uint32_t qa = (uint32_t)(wm16 + (lane & 15)) * QPITCH
                        + ks * 32 + ((lane >> 4) & 1) * 16;
            LDSM_X4(ah, sb + AT_QH + qa);
            LDSM_X4(al, sb + AT_QL + qa);
            #pragma unroll
            for (int j = 0; j < 8; j++) {
                uint32_t b4[4];
                uint32_t ka = (uint32_t)(j * 8 + (lane & 7)) * QPITCH
                            + ks * 32 + ((lane >> 3) & 1) * 16
                            + ((lane >> 4) & 1) * 17408u;
                LDSM_X4(b4, kvb + KV_KH + ka);
                MMA_BF16(s4[j], ah, b4);
                MMA_BF16(s4[j], al, b4);
                MMA_BF16(s4[j], ah, b4 + 2);
            }
        }

        if (kt == qt) {
            int colb = 2 * (lane & 3);
            int rowb = wm16 + (lane >> 2);
            #pragma unroll
            for (int j = 0; j < 8; j++) {
                int c0 = j * 8 + colb;
                if (c0     > rowb)     s4[j][0] = neg_inf();
                if (c0 + 1 > rowb)     s4[j][1] = neg_inf();
                if (c0     > rowb + 8) s4[j][2] = neg_inf();
                if (c0 + 1 > rowb + 8) s4[j][3] = neg_inf();
            }
        }

        float tm0 = neg_inf(), tm1 = neg_inf();
        #pragma unroll
        for (int j = 0; j < 8; j++) {
            tm0 = fmaxf(tm0, fmaxf(s4[j][0], s4[j][1]));
            tm1 = fmaxf(tm1, fmaxf(s4[j][2], s4[j][3]));
        }
        tm0 = fmaxf(tm0, __shfl_xor_sync(0xffffffffu, tm0, 1));
        tm0 = fmaxf(tm0, __shfl_xor_sync(0xffffffffu, tm0, 2));
        tm1 = fmaxf(tm1, __shfl_xor_sync(0xffffffffu, tm1, 1));
        tm1 = fmaxf(tm1, __shfl_xor_sync(0xffffffffu, tm1, 2));
        float mn0 = fmaxf(m0, tm0), mn1 = fmaxf(m1, tm1);
        float a0 = __expf(m0 - mn0), a1 = __expf(m1 - mn1);
        m0 = mn0; m1 = mn1;

        float rs0 = 0.f, rs1 = 0.f;
        uint32_t pah[4][4], pal[4][4];
        #pragma unroll
        for (int j = 0; j < 8; j++) {
            float p0 = __expf(s4[j][0] - mn0), p1 = __expf(s4[j][1] - mn0);
            float p2 = __expf(s4[j][2] - mn1), p3 = __expf(s4[j][3] - mn1);
            rs0 += p0 + p1; rs1 += p2 + p3;
            __nv_bfloat16 b0 = __float2bfloat16(p0), b1 = __float2bfloat16(p1);
            __nv_bfloat16 b2 = __float2bfloat16(p2), b3 = __float2bfloat16(p3);
            uint32_t h01 = ((uint32_t)__bfloat16_as_ushort(b1) << 16) | __bfloat16_as_ushort(b0);
            uint32_t h23 = ((uint32_t)__bfloat16_as_ushort(b3) << 16) | __bfloat16_as_ushort(b2);
            __nv_bfloat16 c0 = __float2bfloat16(p0 - __bfloat162float(b0));
            __nv_bfloat16 c1 = __float2bfloat16(p1 - __bfloat162float(b1));
            __nv_bfloat16 c2 = __float2bfloat16(p2 - __bfloat162float(b2));
            __nv_bfloat16 c3 = __float2bfloat16(p3 - __bfloat162float(b3));
            uint32_t l01 = ((uint32_t)__bfloat16_as_ushort(c1) << 16) | __bfloat16_as_ushort(c0);
            uint32_t l23 = ((uint32_t)__bfloat16_as_ushort(c3) << 16) | __bfloat16_as_ushort(c2);
            int k2 = j >> 1, odd = (j & 1) << 1;
            pah[k2][odd] = h01; pah[k2][odd + 1] = h23;
            pal[k2][odd] = l01; pal[k2][odd + 1] = l23;
        }
        rs0 += __shfl_xor_sync(0xffffffffu, rs0, 1);
        rs0 += __shfl_xor_sync(0xffffffffu, rs0, 2);
        rs1 += __shfl_xor_sync(0xffffffffu, rs1, 1);
        rs1 += __shfl_xor_sync(0xffffffffu, rs1, 2);
        l0 = l0 * a0 + rs0;
        l1 = l1 * a1 + rs1;
        #pragma unroll
        for (int n = 0; n < 16; n++) {
            o[n][0] *= a0; o[n][1] *= a0; o[n][2] *= a1; o[n][3] *= a1;
        }

        #pragma unroll
        for (int ks2 = 0; ks2 < 4; ks2++) {
            #pragma unroll
            for (int n = 0; n < 16; n++) {
                uint32_t v4[4];
                uint32_t va = (uint32_t)(n * 8 + (lane & 7)) * VPITCH
                            + ks2 * 32 + ((lane >> 3) & 1) * 16
                            + ((lane >> 4) & 1) * 18432u;
                LDSM_X4(v4, kvb + KV_VH + va);
                MMA_BF16(o[n], pah[ks2], v4);
                MMA_BF16(o[n], pal[ks2], v4);
                MMA_BF16(o[n], pah[ks2], v4 + 2);
            }
        }
        __syncthreads();
    }

    float inv0 = 1.f / l0, inv1 = 1.f / l1;
    int rg = qt * 64 + wm16 + (lane >> 2);
    int cb = h * 128 + 2 * (lane & 3);
    #pragma unroll
    for (int n = 0; n < 16; n++) {
        float* p0 = out + (size_t)rg * HID + cb + n * 8;
        *(float2*)p0 = make_float2(o[n][0] * inv0, o[n][1] * inv0);
        float* p1 = out + (size_t)(rg + 8) * HID + cb + n * 8;
        *(float2*)p1 = make_float2(o[n][2] * inv1, o[n][3] * inv1);
    }
}

extern "C" void kernel_launch(void* const* d_in, const int* in_sizes, int n_in,
                              void* d_out, int out_size) {
    const float* hidden = (const float*)d_in[0];
    const int*   pos    = (const int*)d_in[1];
    const int*   qkv_qw = (const int*)d_in[2];
    const float* qkv_s  = (const float*)d_in[3];
    const float* qkv_z  = (const float*)d_in[4];
    const int*   o_qw   = (const int*)d_in[5];
    const float* o_s    = (const float*)d_in[6];
    const float* o_z    = (const float*)d_in[7];
    float* out = (float*)d_out;

    void* p;
    cudaGetSymbolAddress(&p, g_proj); float* proj = (float*)p;
    cudaGetSymbolAddress(&p, g_attn); float* attn = (float*)p;
    cudaGetSymbolAddress(&p, g_R);    float* R    = (float*)p;
    cudaGetSymbolAddress(&p, g_ah);   __half* ah  = (__half*)p;
    cudaGetSymbolAddress(&p, g_al);   __half* al  = (__half*)p;
    cudaGetSymbolAddress(&p, g_bq);   __half* bq  = (__half*)p;

    int gemm_smem = 2 * GSTAGE;                       // 131072
    cudaFuncSetAttribute(gemm_q_kernel,
                         cudaFuncAttributeMaxDynamicSharedMemorySize, gemm_smem);
    cudaFuncSetAttribute(attn_mma_kernel,
                         cudaFuncAttributeMaxDynamicSharedMemorySize, AT_SMEM);

    // 1. RoPE tables
    rope_tables_kernel<<<SEQ, 64>>>(pos);

    // 2. prep: activations (hi/lo + group rowsums), exact-q weights, scales
    split_pad_kernel<<<(SEQ * HID) / (256 * 4), 256>>>(hidden, ah, al);
    rowsum_ext_kernel<<<SEQ, 256>>>(hidden, ah, al);
    qT_kernel<<<dim3(QKVN / 64, HID / 64), 256>>>(qkv_qw, bq, QKVN);
    prep_scales_kernel<<<QKVN / 32, 256>>>(qkv_s, qkv_z, R, bq, QKVN);

    // 3. QKV projection (exact-q GEMM)
    gemm_q_kernel<<<dim3(SEQ / 128, QKVN / 256), 256, gemm_smem>>>(
        ah, al, bq, R, proj, SEQ, QKVN);

    // 4. RoPE + split Q/K; transpose + split V
    rope_split_kernel<<<SEQ, 256>>>();
    v_transpose_split_kernel<<<dim3(SEQ / 32, HDIM / 32, HEADS), dim3(32, 8)>>>();

    // 5. causal flash attention
    attn_mma_kernel<<<dim3(HEADS, SEQ / 64), 128, AT_SMEM>>>(attn);

    // 6. prep for O projection (reuse ah/al/bq/R)
    split_pad_kernel<<<(SEQ * HID) / (256 * 4), 256>>>(attn, ah, al);
    rowsum_ext_kernel<<<SEQ, 256>>>(attn, ah, al);
    qT_kernel<<<dim3(HID / 64, HID / 64), 256>>>(o_qw, bq, HID);
    prep_scales_kernel<<<HID / 32, 256>>>(o_s, o_z, R, bq, HID);

    // 7. output projection
    gemm_q_kernel<<<dim3(SEQ / 128, HID / 256), 256, gemm_smem>>>(
        ah, al, bq, R, out, SEQ, HID);
}

// round 16
// speedup vs baseline: 1.2178x; 1.0876x over previous
#include <cuda_runtime.h>
#include <cuda_bf16.h>
#include <cuda_fp16.h>
#include <math.h>
#include <stdint.h>

#define SEQ   2048
#define HID   4096
#define HEADS 32
#define HDIM  128
#define QKVN  12288
#define KPAD  4160          // 4096 + 64 ext cols (zero-correction)
#define NCH64 65            // KPAD / 64

// ---------------- scratch (device globals; no runtime allocation) ----------------
__device__ float g_proj[(size_t)SEQ * QKVN];
__device__ float g_attn[(size_t)SEQ * HID];
__device__ float g_cos[SEQ * 64];
__device__ float g_sin[SEQ * 64];
__device__ float g_R[(size_t)32 * QKVN];                      // telescoping ratios
__device__ __half g_ah[(size_t)SEQ * KPAD];                   // activation hi (fp16)
__device__ __half g_al[(size_t)SEQ * KPAD];                   // activation lo
__device__ __half g_bq[(size_t)QKVN * KPAD];                  // exact q^T + ext cols
__device__ __nv_bfloat16 g_qh[(size_t)HEADS * SEQ * HDIM];
__device__ __nv_bfloat16 g_ql[(size_t)HEADS * SEQ * HDIM];
__device__ __nv_bfloat16 g_kh[(size_t)HEADS * SEQ * HDIM];
__device__ __nv_bfloat16 g_kl[(size_t)HEADS * SEQ * HDIM];
__device__ __nv_bfloat16 g_vth[(size_t)HEADS * HDIM * SEQ];
__device__ __nv_bfloat16 g_vtl[(size_t)HEADS * HDIM * SEQ];

__device__ __forceinline__ float neg_inf() { return __int_as_float(0xff800000); }

__device__ __forceinline__ uint32_t smem_to_u32(const void* p) {
    uint32_t a;
    asm("{ .reg .u64 t; cvta.to.shared.u64 t, %1; cvt.u32.u64 %0, t; }" : "=r"(a) : "l"(p));
    return a;
}
__device__ __forceinline__ void cp_async16(uint32_t dst, const void* src) {
    asm volatile("cp.async.cg.shared.global [%0], [%1], 16;" :: "r"(dst), "l"(src));
}
#define CP_COMMIT() asm volatile("cp.async.commit_group;" ::: "memory")
#define CP_WAIT(n)  asm volatile("cp.async.wait_group %0;" :: "n"(n) : "memory")

#define LDSM_X4(r, a) \
    asm volatile("ldmatrix.sync.aligned.m8n8.x4.shared.b16 {%0,%1,%2,%3}, [%4];" \
        : "=r"((r)[0]), "=r"((r)[1]), "=r"((r)[2]), "=r"((r)[3]) : "r"(a))
#define LDSM_X2(r, a) \
    asm volatile("ldmatrix.sync.aligned.m8n8.x2.shared.b16 {%0,%1}, [%2];" \
        : "=r"((r)[0]), "=r"((r)[1]) : "r"(a))
#define MMA_BF16(d, a, b) \
    asm volatile("mma.sync.aligned.m16n8k16.row.col.f32.bf16.bf16.f32 " \
        "{%0,%1,%2,%3}, {%4,%5,%6,%7}, {%8,%9}, {%0,%1,%2,%3};" \
        : "+f"((d)[0]), "+f"((d)[1]), "+f"((d)[2]), "+f"((d)[3]) \
        : "r"((a)[0]), "r"((a)[1]), "r"((a)[2]), "r"((a)[3]), "r"((b)[0]), "r"((b)[1]))
#define MMA_F16(d, a, b) \
    asm volatile("mma.sync.aligned.m16n8k16.row.col.f32.f16.f16.f32 " \
        "{%0,%1,%2,%3}, {%4,%5,%6,%7}, {%8,%9}, {%0,%1,%2,%3};" \
        : "+f"((d)[0]), "+f"((d)[1]), "+f"((d)[2]), "+f"((d)[3]) \
        : "r"((a)[0]), "r"((a)[1]), "r"((a)[2]), "r"((a)[3]), "r"((b)[0]), "r"((b)[1]))

// 64B-row swizzle (attention tiles, validated)
__device__ __forceinline__ uint32_t swz(int r, int kbyte) {
    uint32_t seg = ((uint32_t)(kbyte >> 4)) ^ (((uint32_t)r >> 1) & 3u);
    return (uint32_t)r * 64u + (seg << 4) + (uint32_t)(kbyte & 15);
}
// 128B-row swizzle (GEMM BK=64 tiles, validated R15)
__device__ __forceinline__ uint32_t swz128(int r, int kbyte) {
    return (uint32_t)r * 128u + ((uint32_t)kbyte ^ (((uint32_t)r & 7u) << 4));
}

// ---------------- RoPE tables ----------------
__global__ void rope_tables_kernel(const int* __restrict__ pos_ids) {
    int s = blockIdx.x;
    int d = threadIdx.x;
    double inv = pow(10000.0, -(double)(2 * d) / 128.0);
    double ang = (double)pos_ids[s] * inv;
    g_cos[s * 64 + d] = (float)cos(ang);
    g_sin[s * 64 + d] = (float)sin(ang);
}

// ---------------- fp32 -> fp16 hi/lo split into padded [M][KPAD] ----------------
__global__ __launch_bounds__(256)
void split_pad_kernel(const float* __restrict__ X, __half* __restrict__ H,
                      __half* __restrict__ L) {
    int i = (blockIdx.x * 256 + threadIdx.x) * 4;
    int r = i >> 12, c = i & 4095;
    float4 v = *(const float4*)(X + i);
    size_t o = (size_t)r * KPAD + c;
    __half h0 = __float2half_rn(v.x), h1 = __float2half_rn(v.y);
    __half h2 = __float2half_rn(v.z), h3 = __float2half_rn(v.w);
    H[o + 0] = h0; H[o + 1] = h1; H[o + 2] = h2; H[o + 3] = h3;
    L[o + 0] = __float2half_rn(v.x - __half2float(h0));
    L[o + 1] = __float2half_rn(v.y - __half2float(h1));
    L[o + 2] = __float2half_rn(v.z - __half2float(h2));
    L[o + 3] = __float2half_rn(v.w - __half2float(h3));
}

// ---------------- per-row per-group sums -> ext cols of A ----------------
__global__ __launch_bounds__(256)
void rowsum_ext_kernel(const float* __restrict__ X, __half* __restrict__ H,
                       __half* __restrict__ L) {
    __shared__ float gs[32];
    int m = blockIdx.x;
    const float* row = X + (size_t)m * 4096;
    int g = threadIdx.x >> 3, l8 = threadIdx.x & 7;
    float s = 0.f;
    #pragma unroll
    for (int j = 0; j < 16; j++) s += row[g * 128 + l8 * 16 + j];
    s += __shfl_xor_sync(0xffffffffu, s, 1);
    s += __shfl_xor_sync(0xffffffffu, s, 2);
    s += __shfl_xor_sync(0xffffffffu, s, 4);
    if (l8 == 0) gs[g] = s;
    __syncthreads();
    if (threadIdx.x < 32) {
        float v = gs[threadIdx.x];
        __half h = __float2half_rn(v);
        __half lo = __float2half_rn(v - __half2float(h));
        size_t o = (size_t)m * KPAD + 4096 + threadIdx.x;
        H[o] = h; H[o + 32] = h;
        L[o] = lo; L[o + 32] = lo;
    }
}

// ---------------- q transpose: coalesced 64x64 tile (validated R13) ----------------
__global__ __launch_bounds__(256)
void qT_kernel(const int* __restrict__ Qw, __half* __restrict__ B, int N) {
    __shared__ int w[64][65];
    int n0 = blockIdx.x * 64, k0 = blockIdx.y * 64;
    int tid = threadIdx.x;
    int tx = tid & 15, ty = tid >> 4;
    #pragma unroll
    for (int p = 0; p < 4; p++) {
        int r = p * 16 + ty;
        int4 v = *(const int4*)(Qw + (size_t)(k0 + r) * N + n0 + tx * 4);
        w[r][tx * 4 + 0] = v.x; w[r][tx * 4 + 1] = v.y;
        w[r][tx * 4 + 2] = v.z; w[r][tx * 4 + 3] = v.w;
    }
    __syncthreads();
    int kx = tid & 7, ny = tid >> 3;
    #pragma unroll
    for (int p = 0; p < 2; p++) {
        int n = p * 32 + ny;
        __half h[8];
        #pragma unroll
        for (int j = 0; j < 8; j++) h[j] = __float2half_rn((float)w[kx * 8 + j][n]);
        *(uint4*)(B + (size_t)(n0 + n) * KPAD + k0 + kx * 8) = *(uint4*)h;
    }
}

// ---------------- scale prep: parallel (validated R12) ----------------
__global__ __launch_bounds__(256)
void prep_scales_kernel(const float* __restrict__ S, const float* __restrict__ Z,
                        float* __restrict__ R, __half* __restrict__ B, int N) {
    __shared__ float sp[32][33];
    int nl = threadIdx.x & 31, tg = threadIdx.x >> 5;
    int n = blockIdx.x * 32 + nl;
    #pragma unroll
    for (int j = 0; j < 4; j++) {
        int g = tg * 4 + j;
        float s = S[(size_t)g * N + n];
        float z = Z[(size_t)g * N + n];
        sp[g][nl] = fmaxf(s, 1e-30f);
        float t = -s * z;
        __half th = __float2half_rn(t);
        B[(size_t)n * KPAD + 4096 + g] = th;
        B[(size_t)n * KPAD + 4128 + g] = __float2half_rn(t - __half2float(th));
    }
    __syncthreads();
    #pragma unroll
    for (int j = 0; j < 4; j++) {
        int g = tg * 4 + j;
        R[(size_t)g * N + n] = (g < 31) ? sp[g][nl] / sp[g + 1][nl] : sp[31][nl];
    }
}

// ---------------- exact-q fp16 GEMM: BK=64, 2-stage, templated N tile = 32*NB ---------
// NB = n-blocks per warp (6 -> 192 tile for QKV wave fit; 8 -> 256 tile for O)
#define GST_AH 0
#define GST_AL 16384
#define GST_B  32768

template <int NB>
__global__ __launch_bounds__(256, 1)
void gemm_q_kernel(const __half* __restrict__ Ah, const __half* __restrict__ Al,
                   const __half* __restrict__ B, const float* __restrict__ R,
                   float* __restrict__ C, int M, int N) {
    constexpr int NTILE   = 32 * NB;              // CTA n extent
    constexpr int BCHUNKS = NTILE * 8 / 256;      // 16B chunks per thread for B
    constexpr int GSTAGE  = 32768 + NTILE * 128;  // A(32K) + B rows*128B
    extern __shared__ char smraw[];
    const uint32_t sb = smem_to_u32(smraw);
    const int tid = threadIdx.x, lane = tid & 31, wid = tid >> 5;
    const int m0 = blockIdx.x << 7, n0 = blockIdx.y * NTILE;
    const int wm = (wid & 1) << 6;
    const int wn = (wid >> 1) * (8 * NB);

    float acc[4][NB][4];
    #pragma unroll
    for (int mi = 0; mi < 4; mi++)
        #pragma unroll
        for (int ni = 0; ni < NB; ni++)
            #pragma unroll
            for (int e = 0; e < 4; e++) acc[mi][ni][e] = 0.f;

    auto load_stage = [&](int buf, int c) {
        uint32_t stage = sb + (uint32_t)buf * GSTAGE;
        int k0 = c << 6;
        #pragma unroll
        for (int u = 0; u < 8; u++) {            // A hi+lo: 2048 x 16B
            int idx = tid + u * 256;
            int hl = idx >> 10;
            int r = (idx & 1023) >> 3, seg = idx & 7;
            const __half* src = hl ? Al : Ah;
            cp_async16(stage + (hl ? GST_AL : GST_AH) + swz128(r, seg << 4),
                       src + (size_t)(m0 + r) * KPAD + k0 + seg * 8);
        }
        #pragma unroll
        for (int u = 0; u < BCHUNKS; u++) {      // B: NTILE rows x 128B
            int idx = tid + u * 256;
            int r = idx >> 3, seg = idx & 7;
            cp_async16(stage + GST_B + swz128(r, seg << 4),
                       B + (size_t)(n0 + r) * KPAD + k0 + seg * 8);
        }
        CP_COMMIT();
    };

    load_stage(0, 0);

    float rv[2 * NB];
    int buf = 0;
    for (int i = 0; i < NCH64; i++) {
        if (i + 1 < NCH64) {
            load_stage(buf ^ 1, i + 1);
            CP_WAIT(1);
        } else {
            CP_WAIT(0);
        }
        __syncthreads();

        if ((i & 1) == 0 && i < 64) {
            int g = i >> 1;
            #pragma unroll
            for (int j = 0; j < 2 * NB; j++)
                rv[j] = __ldg(&R[(size_t)g * N + n0 + wn + (j >> 1) * 8
                                 + (lane & 3) * 2 + (j & 1)]);
        }

        uint32_t stage = sb + (uint32_t)buf * GSTAGE;
        #pragma unroll
        for (int ks = 0; ks < 4; ks++) {
            uint32_t a_h[4][4], a_l[4][4];
            int akb = ks * 32 + ((lane >> 4) & 1) * 16;
            #pragma unroll
            for (int mi = 0; mi < 4; mi++) {
                int row = wm + mi * 16 + (lane & 15);
                uint32_t so = swz128(row, akb);
                LDSM_X4(a_h[mi], stage + GST_AH + so);
                LDSM_X4(a_l[mi], stage + GST_AL + so);
            }
            int bkb = ks * 32 + ((lane >> 3) & 1) * 16;
            #pragma unroll
            for (int np = 0; np < NB / 2; np++) {
                uint32_t b4[4];
                int row = wn + (np * 2 + ((lane >> 4) & 1)) * 8 + (lane & 7);
                LDSM_X4(b4, stage + GST_B + swz128(row, bkb));
                #pragma unroll
                for (int mi = 0; mi < 4; mi++) {
                    MMA_F16(acc[mi][np * 2],     a_h[mi], b4);
                    MMA_F16(acc[mi][np * 2],     a_l[mi], b4);
                    MMA_F16(acc[mi][np * 2 + 1], a_h[mi], b4 + 2);
                    MMA_F16(acc[mi][np * 2 + 1], a_l[mi], b4 + 2);
                }
            }
        }

        if ((i & 1) == 1 && i < 64) {
            #pragma unroll
            for (int mi = 0; mi < 4; mi++)
                #pragma unroll
                for (int ni = 0; ni < NB; ni++) {
                    acc[mi][ni][0] *= rv[ni * 2];
                    acc[mi][ni][1] *= rv[ni * 2 + 1];
                    acc[mi][ni][2] *= rv[ni * 2];
                    acc[mi][ni][3] *= rv[ni * 2 + 1];
                }
        }
        __syncthreads();
        buf ^= 1;
    }

    const int er = m0 + wm + (lane >> 2);
    const int ec = n0 + wn + (lane & 3) * 2;
    #pragma unroll
    for (int mi = 0; mi < 4; mi++) {
        #pragma unroll
        for (int ni = 0; ni < NB; ni++) {
            float* p = C + (size_t)(er + mi * 16) * N + ec + ni * 8;
            *(float2*)p                   = make_float2(acc[mi][ni][0], acc[mi][ni][1]);
            *(float2*)(p + 8 * (size_t)N) = make_float2(acc[mi][ni][2], acc[mi][ni][3]);
        }
    }
}

// ---------------- RoPE + split Q/K -> bf16 hi/lo [h][s][d] ----------------
__global__ __launch_bounds__(256)
void rope_split_kernel() {
    int s = blockIdx.x;
    const float* row = g_proj + (size_t)s * QKVN;
    for (int it = threadIdx.x; it < 4096; it += 256) {
        int qk = it >> 11;
        int hh = (it >> 6) & 31;
        int d  = it & 63;
        float c = g_cos[s * 64 + d], sn = g_sin[s * 64 + d];
        const float* p = row + qk * HID + hh * 128;
        float x1 = p[d], x2 = p[d + 64];
        float y1 = x1 * c - x2 * sn;
        float y2 = x2 * c + x1 * sn;
        if (qk == 0) { y1 *= 0.08838834764831845f; y2 *= 0.08838834764831845f; }
        __nv_bfloat16* H = qk ? g_kh : g_qh;
        __nv_bfloat16* L = qk ? g_kl : g_ql;
        size_t o = ((size_t)hh * SEQ + s) * 128 + d;
        __nv_bfloat16 h1 = __float2bfloat16(y1), h2 = __float2bfloat16(y2);
        H[o] = h1; H[o + 64] = h2;
        L[o]      = __float2bfloat16(y1 - __bfloat162float(h1));
        L[o + 64] = __float2bfloat16(y2 - __bfloat162float(h2));
    }
}

// ---------------- V transpose + split ----------------
__global__ void v_transpose_split_kernel() {
    __shared__ float t[32][33];
    int s0 = blockIdx.x * 32, d0 = blockIdx.y * 32, h = blockIdx.z;
    int tx = threadIdx.x, ty = threadIdx.y;
    #pragma unroll
    for (int rr = 0; rr < 32; rr += 8)
        t[rr + ty][tx] = g_proj[(size_t)(s0 + rr + ty) * QKVN + 2 * HID + h * 128 + d0 + tx];
    __syncthreads();
    #pragma unroll
    for (int rr = 0; rr < 32; rr += 8) {
        int d = d0 + rr + ty;
        float v = t[tx][rr + ty];
        __nv_bfloat16 hi = __float2bfloat16(v);
        size_t o = ((size_t)h * 128 + d) * SEQ + s0 + tx;
        g_vth[o] = hi;
        g_vtl[o] = __float2bfloat16(v - __bfloat162float(hi));
    }
}

// ---------------- bf16x3 mma.sync flash attention (R15 exact) ----------------
#define QPITCH 272
#define VPITCH 144
#define AT_QH  0
#define AT_QL  17408
#define AT_K0  34816
#define KV_KH  0
#define KV_KL  17408
#define KV_VH  34816
#define KV_VL  53248
#define AT_STAGE 71680
#define AT_SMEM  (AT_K0 + 2 * AT_STAGE)

__global__ __launch_bounds__(128, 1)
void attn_mma_kernel(float* __restrict__ out) {
    extern __shared__ char smraw[];
    const uint32_t sb = smem_to_u32(smraw);
    const int h  = blockIdx.x;
    const int qt = (int)gridDim.y - 1 - (int)blockIdx.y;
    const int tid = threadIdx.x, lane = tid & 31, warp = tid >> 5;
    const int wm16 = warp << 4;

    const __nv_bfloat16* qhp = g_qh + ((size_t)h * SEQ + qt * 64) * 128;
    const __nv_bfloat16* qlp = g_ql + ((size_t)h * SEQ + qt * 64) * 128;
    const __nv_bfloat16* kh0 = g_kh + (size_t)h * SEQ * 128;
    const __nv_bfloat16* kl0 = g_kl + (size_t)h * SEQ * 128;
    const __nv_bfloat16* vh0 = g_vth + (size_t)h * 128 * SEQ;
    const __nv_bfloat16* vl0 = g_vtl + (size_t)h * 128 * SEQ;

    auto load_kv = [&](int kt_, int buf_) {
        uint32_t base = sb + AT_K0 + (uint32_t)buf_ * AT_STAGE;
        const __nv_bfloat16* kh = kh0 + (size_t)kt_ * 64 * 128;
        const __nv_bfloat16* kl = kl0 + (size_t)kt_ * 64 * 128;
        #pragma unroll
        for (int u = 0; u < 16; u++) {
            int i = tid + u * 128;
            int m = i >> 10, c = i & 1023, r = c >> 4, seg = c & 15;
            cp_async16(base + m * 17408 + r * QPITCH + seg * 16,
                       (m ? kl : kh) + r * 128 + seg * 8);
        }
        const __nv_bfloat16* vh = vh0 + kt_ * 64;
        const __nv_bfloat16* vl = vl0 + kt_ * 64;
        #pragma unroll
        for (int u = 0; u < 16; u++) {
            int i = tid + u * 128;
            int m = i >> 10, c = i & 1023, r = c >> 3, seg = c & 7;
            cp_async16(base + KV_VH + m * 18432 + r * VPITCH + seg * 16,
                       (m ? vl : vh) + (size_t)r * SEQ + seg * 8);
        }
    };

    #pragma unroll
    for (int u = 0; u < 16; u++) {
        int i = tid + u * 128;
        int m = i >> 10, c = i & 1023, r = c >> 4, seg = c & 15;
        const __nv_bfloat16* src = m ? qlp : qhp;
        cp_async16(sb + (m ? AT_QL : AT_QH) + r * QPITCH + seg * 16,
                   src + r * 128 + seg * 8);
    }
    load_kv(0, 0);
    CP_COMMIT();

    float o[16][4];
    #pragma unroll
    for (int n = 0; n < 16; n++)
        #pragma unroll
        for (int e = 0; e < 4; e++) o[n][e] = 0.f;
    float m0 = neg_inf(), m1 = neg_inf(), l0 = 0.f, l1 = 0.f;

    for (int kt = 0; kt <= qt; kt++) {
        int buf = kt & 1;
        if (kt < qt) {
            load_kv(kt + 1, buf ^ 1);
            CP_COMMIT();
            CP_WAIT(1);
        } else {
            CP_WAIT(0);
        }
        __syncthreads();

        uint32_t kvb = sb + AT_K0 + (uint32_t)buf * AT_STAGE;

        float s4[8][4];
        #pragma unroll
        for (int j = 0; j < 8; j++)
            #pragma unroll
            for (int e = 0; e < 4; e++) s4[j][e] = 0.f;
        #pragma unroll
        for (int ks = 0; ks < 8; ks++) {
            uint32_t ah[4], al[4];
            uint32_t qa = (uint32_t)(wm16 + (lane & 15)) * QPITCH
                        + ks * 32 + ((lane >> 4) & 1) * 16;
            LDSM_X4(ah, sb + AT_QH + qa);
            LDSM_X4(al, sb + AT_QL + qa);
            #pragma unroll
            for (int j = 0; j < 8; j++) {
                uint32_t b4[4];
                uint32_t ka = (uint32_t)(j * 8 + (lane & 7)) * QPITCH
                            + ks * 32 + ((lane >> 3) & 1) * 16
                            + ((lane >> 4) & 1) * 17408u;
                LDSM_X4(b4, kvb + KV_KH + ka);
                MMA_BF16(s4[j], ah, b4);
                MMA_BF16(s4[j], al, b4);
                MMA_BF16(s4[j], ah, b4 + 2);
            }
        }

        if (kt == qt) {
            int colb = 2 * (lane & 3);
            int rowb = wm16 + (lane >> 2);
            #pragma unroll
            for (int j = 0; j < 8; j++) {
                int c0 = j * 8 + colb;
                if (c0     > rowb)     s4[j][0] = neg_inf();
                if (c0 + 1 > rowb)     s4[j][1] = neg_inf();
                if (c0     > rowb + 8) s4[j][2] = neg_inf();
                if (c0 + 1 > rowb + 8) s4[j][3] = neg_inf();
            }
        }

        float tm0 = neg_inf(), tm1 = neg_inf();
        #pragma unroll
        for (int j = 0; j < 8; j++) {
            tm0 = fmaxf(tm0, fmaxf(s4[j][0], s4[j][1]));
            tm1 = fmaxf(tm1, fmaxf(s4[j][2], s4[j][3]));
        }
        tm0 = fmaxf(tm0, __shfl_xor_sync(0xffffffffu, tm0, 1));
        tm0 = fmaxf(tm0, __shfl_xor_sync(0xffffffffu, tm0, 2));
        tm1 = fmaxf(tm1, __shfl_xor_sync(0xffffffffu, tm1, 1));
        tm1 = fmaxf(tm1, __shfl_xor_sync(0xffffffffu, tm1, 2));
        float mn0 = fmaxf(m0, tm0), mn1 = fmaxf(m1, tm1);
        float a0 = __expf(m0 - mn0), a1 = __expf(m1 - mn1);
        m0 = mn0; m1 = mn1;

        float rs0 = 0.f, rs1 = 0.f;
        uint32_t pah[4][4], pal[4][4];
        #pragma unroll
        for (int j = 0; j < 8; j++) {
            float p0 = __expf(s4[j][0] - mn0), p1 = __expf(s4[j][1] - mn0);
            float p2 = __expf(s4[j][2] - mn1), p3 = __expf(s4[j][3] - mn1);
            rs0 += p0 + p1; rs1 += p2 + p3;
            __nv_bfloat16 b0 = __float2bfloat16(p0), b1 = __float2bfloat16(p1);
            __nv_bfloat16 b2 = __float2bfloat16(p2), b3 = __float2bfloat16(p3);
            uint32_t h01 = ((uint32_t)__bfloat16_as_ushort(b1) << 16) | __bfloat16_as_ushort(b0);
            uint32_t h23 = ((uint32_t)__bfloat16_as_ushort(b3) << 16) | __bfloat16_as_ushort(b2);
            __nv_bfloat16 c0 = __float2bfloat16(p0 - __bfloat162float(b0));
            __nv_bfloat16 c1 = __float2bfloat16(p1 - __bfloat162float(b1));
            __nv_bfloat16 c2 = __float2bfloat16(p2 - __bfloat162float(b2));
            __nv_bfloat16 c3 = __float2bfloat16(p3 - __bfloat162float(b3));
            uint32_t l01 = ((uint32_t)__bfloat16_as_ushort(c1) << 16) | __bfloat16_as_ushort(c0);
            uint32_t l23 = ((uint32_t)__bfloat16_as_ushort(c3) << 16) | __bfloat16_as_ushort(c2);
            int k2 = j >> 1, odd = (j & 1) << 1;
            pah[k2][odd] = h01; pah[k2][odd + 1] = h23;
            pal[k2][odd] = l01; pal[k2][odd + 1] = l23;
        }
        rs0 += __shfl_xor_sync(0xffffffffu, rs0, 1);
        rs0 += __shfl_xor_sync(0xffffffffu, rs0, 2);
        rs1 += __shfl_xor_sync(0xffffffffu, rs1, 1);
        rs1 += __shfl_xor_sync(0xffffffffu, rs1, 2);
        l0 = l0 * a0 + rs0;
        l1 = l1 * a1 + rs1;
        #pragma unroll
        for (int n = 0; n < 16; n++) {
            o[n][0] *= a0; o[n][1] *= a0; o[n][2] *= a1; o[n][3] *= a1;
        }

        #pragma unroll
        for (int ks2 = 0; ks2 < 4; ks2++) {
            #pragma unroll
            for (int n = 0; n < 16; n++) {
                uint32_t v4[4];
                uint32_t va = (uint32_t)(n * 8 + (lane & 7)) * VPITCH
                            + ks2 * 32 + ((lane >> 3) & 1) * 16
                            + ((lane >> 4) & 1) * 18432u;
                LDSM_X4(v4, kvb + KV_VH + va);
                MMA_BF16(o[n], pah[ks2], v4);
                MMA_BF16(o[n], pal[ks2], v4);
                MMA_BF16(o[n], pah[ks2], v4 + 2);
            }
        }
        __syncthreads();
    }

    float inv0 = 1.f / l0, inv1 = 1.f / l1;
    int rg = qt * 64 + wm16 + (lane >> 2);
    int cb = h * 128 + 2 * (lane & 3);
    #pragma unroll
    for (int n = 0; n < 16; n++) {
        float* p0 = out + (size_t)rg * HID + cb + n * 8;
        *(float2*)p0 = make_float2(o[n][0] * inv0, o[n][1] * inv0);
        float* p1 = out + (size_t)(rg + 8) * HID + cb + n * 8;
        *(float2*)p1 = make_float2(o[n][2] * inv1, o[n][3] * inv1);
    }
}

extern "C" void kernel_launch(void* const* d_in, const int* in_sizes, int n_in,
                              void* d_out, int out_size) {
    const float* hidden = (const float*)d_in[0];
    const int*   pos    = (const int*)d_in[1];
    const int*   qkv_qw = (const int*)d_in[2];
    const float* qkv_s  = (const float*)d_in[3];
    const float* qkv_z  = (const float*)d_in[4];
    const int*   o_qw   = (const int*)d_in[5];
    const float* o_s    = (const float*)d_in[6];
    const float* o_z    = (const float*)d_in[7];
    float* out = (float*)d_out;

    void* p;
    cudaGetSymbolAddress(&p, g_proj); float* proj = (float*)p;
    cudaGetSymbolAddress(&p, g_attn); float* attn = (float*)p;
    cudaGetSymbolAddress(&p, g_R);    float* R    = (float*)p;
    cudaGetSymbolAddress(&p, g_ah);   __half* ah  = (__half*)p;
    cudaGetSymbolAddress(&p, g_al);   __half* al  = (__half*)p;
    cudaGetSymbolAddress(&p, g_bq);   __half* bq  = (__half*)p;

    int smem6 = 2 * (32768 + 192 * 128);              // 114688 (NB=6)
    int smem8 = 2 * (32768 + 256 * 128);              // 131072 (NB=8)
    cudaFuncSetAttribute(gemm_q_kernel<6>,
                         cudaFuncAttributeMaxDynamicSharedMemorySize, smem6);
    cudaFuncSetAttribute(gemm_q_kernel<8>,
                         cudaFuncAttributeMaxDynamicSharedMemorySize, smem8);
    cudaFuncSetAttribute(attn_mma_kernel,
                         cudaFuncAttributeMaxDynamicSharedMemorySize, AT_SMEM);

    // 1. RoPE tables
    rope_tables_kernel<<<SEQ, 64>>>(pos);

    // 2. prep: activations (hi/lo + group rowsums), exact-q weights, scales
    split_pad_kernel<<<(SEQ * HID) / (256 * 4), 256>>>(hidden, ah, al);
    rowsum_ext_kernel<<<SEQ, 256>>>(hidden, ah, al);
    qT_kernel<<<dim3(QKVN / 64, HID / 64), 256>>>(qkv_qw, bq, QKVN);
    prep_scales_kernel<<<QKVN / 32, 256>>>(qkv_s, qkv_z, R, bq, QKVN);

    // 3. QKV projection: 128x192 tiles -> 1024 CTAs (6.92 waves, ~1% tail waste)
    gemm_q_kernel<6><<<dim3(SEQ / 128, QKVN / 192), 256, smem6>>>(
        ah, al, bq, R, proj, SEQ, QKVN);

    // 4. RoPE + split Q/K; transpose + split V
    rope_split_kernel<<<SEQ, 256>>>();
    v_transpose_split_kernel<<<dim3(SEQ / 32, HDIM / 32, HEADS), dim3(32, 8)>>>();

    // 5. causal flash attention
    attn_mma_kernel<<<dim3(HEADS, SEQ / 64), 128, AT_SMEM>>>(attn);

    // 6. prep for O projection (reuse ah/al/bq/R)
    split_pad_kernel<<<(SEQ * HID) / (256 * 4), 256>>>(attn, ah, al);
    rowsum_ext_kernel<<<SEQ, 256>>>(attn, ah, al);
    qT_kernel<<<dim3(HID / 64, HID / 64), 256>>>(o_qw, bq, HID);
    prep_scales_kernel<<<HID / 32, 256>>>(o_s, o_z, R, bq, HID);

    // 7. output projection: keep 128x256 (best integer fit for N=4096)
    gemm_q_kernel<8><<<dim3(SEQ / 128, HID / 256), 256, smem8>>>(
        ah, al, bq, R, out, SEQ, HID);
}